// round 11
// baseline (speedup 1.0000x reference)
#include <cuda_runtime.h>
#include <cuda_fp16.h>
#include <cstdint>

// Problem constants
#define M_TOK   131072      // b*s*a = 2*32*2048
#define EMB     512
#define NHEAD   8
#define HDIM    64
#define NGROUP  512         // b*s*h = 64*8
#define ALEN    2048
#define EPS_F   1e-6f

// Scratch (device globals: allocation-free per harness rules)
__device__ __half   g_iqh[(size_t)M_TOK * EMB];
__device__ __half   g_ikh[(size_t)M_TOK * EMB];
__device__ __half   g_Qh [(size_t)M_TOK * EMB];
__device__ __half   g_Kh [(size_t)M_TOK * EMB];
__device__ __half   g_Vh [(size_t)M_TOK * EMB];
__device__ __half   g_AOh[(size_t)M_TOK * EMB];
__device__ float    g_KtV [(size_t)NGROUP * HDIM * HDIM];
__device__ float    g_ksum[(size_t)NGROUP * HDIM];
__device__ uint32_t g_Wf [4 * (size_t)131072];   // fragment-packed fp16 weights

// ---------------------------------------------------------------------------
__device__ __forceinline__ void mma16(float* d, const uint32_t* a, const uint32_t* b) {
    asm volatile(
        "mma.sync.aligned.m16n8k16.row.col.f32.f16.f16.f32 "
        "{%0,%1,%2,%3},{%4,%5,%6,%7},{%8,%9},{%0,%1,%2,%3};"
        : "+f"(d[0]), "+f"(d[1]), "+f"(d[2]), "+f"(d[3])
        : "r"(a[0]), "r"(a[1]), "r"(a[2]), "r"(a[3]),
          "r"(b[0]), "r"(b[1]));
}

__device__ __forceinline__ void ldmx4(uint32_t* r, uint32_t addr) {
    asm volatile("ldmatrix.sync.aligned.m8n8.x4.shared.b16 {%0,%1,%2,%3}, [%4];"
                 : "=r"(r[0]), "=r"(r[1]), "=r"(r[2]), "=r"(r[3]) : "r"(addr));
}
__device__ __forceinline__ void ldmx4t(uint32_t* r, uint32_t addr) {
    asm volatile("ldmatrix.sync.aligned.m8n8.x4.trans.shared.b16 {%0,%1,%2,%3}, [%4];"
                 : "=r"(r[0]), "=r"(r[1]), "=r"(r[2]), "=r"(r[3]) : "r"(addr));
}
__device__ __forceinline__ void ldmx2t(uint32_t* r, uint32_t addr) {
    asm volatile("ldmatrix.sync.aligned.m8n8.x2.trans.shared.b16 {%0,%1}, [%2];"
                 : "=r"(r[0]), "=r"(r[1]) : "r"(addr));
}

__device__ __forceinline__ uint32_t smem_u32(const void* p) {
    uint32_t a;
    asm("{ .reg .u64 t; cvta.to.shared.u64 t, %1; cvt.u32.u64 %0, t; }"
        : "=r"(a) : "l"(p));
    return a;
}

__device__ __forceinline__ void cp16(uint32_t dst, const void* src) {
    asm volatile("cp.async.cg.shared.global [%0], [%1], 16;"
                 :: "r"(dst), "l"(src) : "memory");
}
#define CP_COMMIT() asm volatile("cp.async.commit_group;" ::: "memory")
#define CP_WAIT1()  asm volatile("cp.async.wait_group 1;" ::: "memory")
#define CP_WAIT0()  asm volatile("cp.async.wait_group 0;" ::: "memory")

__device__ __forceinline__ uint32_t packh2(float a, float b) {
    __half2 h = __floats2half2_rn(a, b);
    return *(uint32_t*)&h;
}

// Fragment mapping (m16n8k16, validated):
//   A: lane l, reg rg: pairs A[(l>>2)+8*(rg&1)][(l&3)*2 + 8*(rg>>1) + {0,1}]
//   B: lane l, reg rg: pairs B[k=(l&3)*2+8*rg+{0,1}][n=(l>>2)]
//   C: lane l, reg c:  row=(l>>2)+8*(c>>1), col=(l&3)*2+(c&1)

// ===========================================================================
// Prep: fp32 -> fp16 for both inputs in ONE launch
// ===========================================================================
#define APREP_BLKS_PER 32768
__global__ __launch_bounds__(256)
void aprep2_kernel(const float* __restrict__ s0, __half* __restrict__ d0,
                   const float* __restrict__ s1, __half* __restrict__ d1)
{
    const int b = blockIdx.x;
    const float* src = (b < APREP_BLKS_PER) ? s0 : s1;
    __half*      dst = (b < APREP_BLKS_PER) ? d0 : d1;
    const size_t i = ((size_t)(b & (APREP_BLKS_PER - 1)) * 256 + threadIdx.x) * 8;
    const float4 a = *(const float4*)(src + i);
    const float4 c = *(const float4*)(src + i + 4);
    __half2 h[4];
    h[0] = __floats2half2_rn(a.x, a.y);
    h[1] = __floats2half2_rn(a.z, a.w);
    h[2] = __floats2half2_rn(c.x, c.y);
    h[3] = __floats2half2_rn(c.z, c.w);
    *(uint4*)(dst + i) = *(uint4*)h;
}

// ===========================================================================
// Weight prep — all 4 weights in ONE launch (grid 2048, weight = blk>>9)
// ===========================================================================
__global__ __launch_bounds__(256)
void wprep4_kernel(const float* __restrict__ W0, const float* __restrict__ W1,
                   const float* __restrict__ W2, const float* __restrict__ W3,
                   uint32_t* __restrict__ Wf)
{
    const int w   = blockIdx.x >> 9;
    const float* W = (w == 0) ? W0 : (w == 1) ? W1 : (w == 2) ? W2 : W3;
    const int o   = (blockIdx.x & 511) * 256 + threadIdx.x;   // 0..131071
    const int rg  = o & 1;
    const int l   = (o >> 1) & 31;
    const int ntg = (o >> 6) & 63;
    const int ks  = (o >> 12) & 3;
    const int c   = o >> 14;
    const int k0  = c * 64 + ks * 16 + (l & 3) * 2 + 8 * rg;
    const int n   = ntg * 8 + (l >> 2);
    Wf[(size_t)w * 131072 + o] =
        packh2(W[(size_t)k0 * EMB + n], W[(size_t)(k0 + 1) * EMB + n]);
}

// ===========================================================================
// fp16 mma GEMM — 64x64 warp tile to halve smem bytes/mma.
// CTA tile BM=128, BN=256, BK=64. 256 threads = 8 warps (2 M x 4 N).
// 3-stage cp.async pipeline; stage = A(128x144B) + B(32KB) = 51200 B.
// KV=0: grid.x=2, C = act(A @ Wf[bx]) + bias
// KV=1: grid.x=4 fused K/V: bx<2 -> K (elu+1, ->Cv0), bx>=2 -> V (->Cv1)
// ===========================================================================
#define AS_B    144
#define A_STG   (128 * 36)            // 4608 words
#define B_STG   8192                  // words (32 ntg x 4 ks x 32 x 2)
#define STG_W   (A_STG + B_STG)       // 12800 words
#define GEMM_SMEM (3 * STG_W * 4)     // 153600 B

template<int ACT, int OUTH, int KV>
__global__ __launch_bounds__(256)
void gemm_h_kernel(const __half* __restrict__ Ah,
                   const uint32_t* __restrict__ WfBase,
                   const float* __restrict__ bias0,
                   const float* __restrict__ bias1,
                   void* __restrict__ Cv0,
                   void* __restrict__ Cv1)
{
    extern __shared__ uint32_t sm[];
    const uint32_t smb = smem_u32(sm);

    const int t   = threadIdx.x;
    const int lid = t & 31;
    const int wid = t >> 5;
    const int wr  = wid >> 2;                      // 0..1 (M, 64 rows each)
    const int wc  = wid & 3;                       // 0..3 (N, 64 cols each)
    const int bxr = blockIdx.x;                    // 0..1 or 0..3
    const int isV = KV ? (bxr >= 2) : 0;
    const int bx  = KV ? (bxr & 1) : bxr;          // 0..1 (N half of 512)
    const int bm  = blockIdx.y * 128;

    const uint32_t* Wf = WfBase + (KV && isV ? (size_t)131072 : 0);
    const float* bias  = (KV && isV) ? bias1 : bias0;
    void* Cv           = (KV && isV) ? Cv1 : Cv0;
    const int act      = KV ? !isV : ACT;

    const uint4* W4 = (const uint4*)Wf;

    auto issue = [&](int c, int s) {
        const uint32_t st = smb + (uint32_t)s * (STG_W * 4);
        // A: 128 rows x 64 fp16 = 1024 x 16B
        #pragma unroll
        for (int i = 0; i < 4; i++) {
            const int id  = t + i * 256;
            const int row = id >> 3;
            const int j   = id & 7;
            cp16(st + row * AS_B + j * 16,
                 Ah + (size_t)(bm + row) * EMB + c * 64 + j * 8);
        }
        // B: 2048 x 16B (32 ntg slice)
        #pragma unroll
        for (int i = 0; i < 8; i++) {
            const int id   = t + i * 256;
            const int ks   = id >> 9;
            const int rest = id & 511;
            cp16(st + (A_STG + ks * 2048) * 4 + rest * 16,
                 W4 + (size_t)((c * 4 + ks) * 64 + bx * 32) * 16 + rest);
        }
        CP_COMMIT();
    };

    float acc[4][8][4];
    #pragma unroll
    for (int i = 0; i < 4; i++)
        #pragma unroll
        for (int j = 0; j < 8; j++)
            #pragma unroll
            for (int k = 0; k < 4; k++)
                acc[i][j][k] = 0.f;

    issue(0, 0);
    issue(1, 1);

    for (int c = 0; c < 8; c++) {
        const int s = c % 3;
        if (c >= 6) { CP_WAIT0(); } else { CP_WAIT1(); }
        __syncthreads();
        if (c + 2 < 8) issue(c + 2, (c + 2) % 3);

        const uint32_t stA = smb + (uint32_t)s * (STG_W * 4);
        const uint32_t* Bb = sm + s * STG_W + A_STG;

        #pragma unroll
        for (int ks = 0; ks < 4; ks++) {
            uint32_t aF[4][4];
            #pragma unroll
            for (int m2 = 0; m2 < 4; m2++)
                ldmx4(aF[m2], stA + (wr * 64 + m2 * 16 + (lid & 15)) * AS_B
                               + ks * 32 + (lid >> 4) * 16);
            // bF transient per n-tile (keeps registers bounded)
            #pragma unroll
            for (int n2 = 0; n2 < 8; n2++) {
                uint32_t bF[2];
                const uint2 v = *(const uint2*)
                    &Bb[ks * 2048 + (wc * 8 + n2) * 64 + lid * 2];
                bF[0] = v.x; bF[1] = v.y;
                #pragma unroll
                for (int m2 = 0; m2 < 4; m2++)
                    mma16(acc[m2][n2], aF[m2], bF);
            }
        }
    }

    const int bn = bx * 256;
    const int r0 = bm + wr * 64 + (lid >> 2);
    #pragma unroll
    for (int m2 = 0; m2 < 4; m2++) {
        const int row = r0 + m2 * 16;
        #pragma unroll
        for (int n2 = 0; n2 < 8; n2++) {
            const int col = bn + wc * 64 + n2 * 8 + (lid & 3) * 2;
            const float b0 = __ldg(bias + col);
            const float b1 = __ldg(bias + col + 1);
            float v0 = acc[m2][n2][0] + b0;
            float v1 = acc[m2][n2][1] + b1;
            float v2 = acc[m2][n2][2] + b0;
            float v3 = acc[m2][n2][3] + b1;
            if (act) {
                v0 = v0 > 0.f ? v0 + 1.f : expf(v0);
                v1 = v1 > 0.f ? v1 + 1.f : expf(v1);
                v2 = v2 > 0.f ? v2 + 1.f : expf(v2);
                v3 = v3 > 0.f ? v3 + 1.f : expf(v3);
            }
            if (OUTH) {
                __half* Ch = (__half*)Cv;
                *(uint32_t*)(Ch + (size_t)row * EMB + col)       = packh2(v0, v1);
                *(uint32_t*)(Ch + (size_t)(row + 8) * EMB + col) = packh2(v2, v3);
            } else {
                float* Cf = (float*)Cv;
                float2 o0; o0.x = v0; o0.y = v1;
                float2 o1; o1.x = v2; o1.y = v3;
                *(float2*)(Cf + (size_t)row * EMB + col) = o0;
                *(float2*)(Cf + (size_t)(row + 8) * EMB + col) = o1;
            }
        }
    }
}

// ===========================================================================
// Tensorized KtV + ksum (unchanged, validated)
// ===========================================================================
#define KTV_KST   9216
#define KTV_VST   11264
#define KTV_STG   (KTV_KST + KTV_VST)
#define KTV_SMEM  (3 * KTV_STG)

__global__ __launch_bounds__(256)
void ktv_mma_kernel(const __half* __restrict__ Kp,
                    const __half* __restrict__ Vp,
                    float* __restrict__ KtV,
                    float* __restrict__ ksum)
{
    extern __shared__ uint32_t sm[];
    const uint32_t smb = smem_u32(sm);

    const int g  = blockIdx.x;
    const int bs = g >> 3;
    const int h  = g & 7;
    const size_t rowbase = (size_t)bs * ALEN;
    const int coff = h * HDIM;

    const int t   = threadIdx.x;
    const int lid = t & 31;
    const int wid = t >> 5;
    const int mt  = wid >> 1;
    const int nh  = wid & 1;
    const int ntc = 5 - nh;
    const int n0  = nh * 40;

    if (t < 64) {
        #pragma unroll
        for (int s = 0; s < 3; s++) {
            __half* vb = (__half*)((char*)sm + s * KTV_STG + KTV_KST);
            vb[t * 88 + 64] = __float2half(1.0f);
        }
    }

    auto issue = [&](int c, int s) {
        const uint32_t stK = smb + (uint32_t)s * KTV_STG;
        const uint32_t stV = stK + KTV_KST;
        const int a0 = c * 64;
        #pragma unroll
        for (int i = 0; i < 2; i++) {
            const int id  = t + i * 256;
            const int row = id >> 3;
            const int j   = id & 7;
            const size_t goff = (rowbase + a0 + row) * EMB + coff + j * 8;
            cp16(stK + row * 144 + j * 16, Kp + goff);
            cp16(stV + row * 176 + j * 16, Vp + goff);
        }
        CP_COMMIT();
    };

    float acc[5][4];
    #pragma unroll
    for (int i = 0; i < 5; i++)
        #pragma unroll
        for (int j = 0; j < 4; j++)
            acc[i][j] = 0.f;

    const int g2 = lid >> 3;
    const int l8 = lid & 7;
    const int a_rowA = (g2 >> 1) * 8 + l8;
    const int a_colA = mt * 16 + (g2 & 1) * 8;
    const int a_rowB = (g2 & 1) * 8 + l8;
    const int a_colB = (g2 >> 1) * 8;
    const int a_rowB2 = ((lid >> 3) & 1) * 8 + l8;

    issue(0, 0);
    issue(1, 1);

    for (int c = 0; c < 32; c++) {
        const int s = c % 3;
        if (c >= 30) { CP_WAIT0(); } else { CP_WAIT1(); }
        __syncthreads();
        if (c + 2 < 32) issue(c + 2, (c + 2) % 3);

        const uint32_t stK = smb + (uint32_t)s * KTV_STG;
        const uint32_t stV = stK + KTV_KST;

        #pragma unroll
        for (int ks = 0; ks < 4; ks++) {
            uint32_t aF[4];
            ldmx4t(aF, stK + (ks * 16 + a_rowA) * 144 + a_colA * 2);

            uint32_t bF[5][2];
            {
                uint32_t r4[4];
                ldmx4t(r4, stV + (ks * 16 + a_rowB) * 176 + (n0 + a_colB) * 2);
                bF[0][0] = r4[0]; bF[0][1] = r4[1];
                bF[1][0] = r4[2]; bF[1][1] = r4[3];
                ldmx4t(r4, stV + (ks * 16 + a_rowB) * 176 + (n0 + 16 + a_colB) * 2);
                bF[2][0] = r4[0]; bF[2][1] = r4[1];
                bF[3][0] = r4[2]; bF[3][1] = r4[3];
            }
            if (nh == 0) {
                uint32_t r2[2];
                ldmx2t(r2, stV + (ks * 16 + a_rowB2) * 176 + (n0 + 32) * 2);
                bF[4][0] = r2[0]; bF[4][1] = r2[1];
            }

            #pragma unroll
            for (int nt = 0; nt < 4; nt++)
                mma16(acc[nt], aF, bF[nt]);
            if (nh == 0)
                mma16(acc[4], aF, bF[4]);
        }
    }

    const int d0 = mt * 16 + (lid >> 2);
    float* Kout = KtV + (size_t)g * HDIM * HDIM;
    #pragma unroll
    for (int nt = 0; nt < 5; nt++) {
        if (nt >= ntc) break;
        const int n = n0 + nt * 8;
        if (n < 64) {
            const int col = n + (lid & 3) * 2;
            float2 o0; o0.x = acc[nt][0]; o0.y = acc[nt][1];
            float2 o1; o1.x = acc[nt][2]; o1.y = acc[nt][3];
            *(float2*)(Kout + d0 * HDIM + col) = o0;
            *(float2*)(Kout + (d0 + 8) * HDIM + col) = o1;
        } else {
            if ((lid & 3) == 0) {
                ksum[(size_t)g * HDIM + d0]     = acc[nt][0];
                ksum[(size_t)g * HDIM + d0 + 8] = acc[nt][2];
            }
        }
    }
}

// ===========================================================================
// fp16 tensorized apply (unchanged, validated)
// ===========================================================================
#define AQ_B  144
#define SM_S  72
#define APPLY_SMEM ((128 * 36 + 32 * SM_S) * 4)

__global__ __launch_bounds__(256, 4)
void apply_h_kernel(const __half* __restrict__ Qp,
                    const float* __restrict__ KtV,
                    const float* __restrict__ ksum,
                    __half* __restrict__ AO)
{
    extern __shared__ uint32_t sm[];
    const uint32_t sQb = smem_u32(sm);
    uint32_t* sM = sm + 128 * 36;

    const int g    = blockIdx.y;
    const int tile = blockIdx.x;
    const int bs   = g >> 3;
    const int h    = g & 7;
    const int t    = threadIdx.x;
    const int lid  = t & 31;
    const int wid  = t >> 5;

    {
        const float* Ksrc = KtV + (size_t)g * HDIM * HDIM;
        #pragma unroll
        for (int i = t; i < 32 * 64; i += 256) {
            const int d2 = i >> 6;
            const int e  = i & 63;
            sM[d2 * SM_S + e] = packh2(Ksrc[(2 * d2) * HDIM + e],
                                       Ksrc[(2 * d2 + 1) * HDIM + e]);
        }
        if (t < 32)
            sM[t * SM_S + 64] = packh2(ksum[(size_t)g * HDIM + 2 * t],
                                       ksum[(size_t)g * HDIM + 2 * t + 1]);
        if (t < 224) {
            const int d2 = t / 7;
            const int e  = 65 + t % 7;
            sM[d2 * SM_S + e] = 0u;
        }
    }
    {
        #pragma unroll
        for (int i = 0; i < 4; i++) {
            const int id  = t + i * 256;
            const int row = id >> 3;
            const int j   = id & 7;
            const uint4 v = *(const uint4*)
                (Qp + ((size_t)bs * ALEN + tile * 128 + row) * EMB + h * HDIM + j * 8);
            *(uint4*)((char*)sm + row * AQ_B + j * 16) = v;
        }
    }
    __syncthreads();

    float acc[9][4];
    #pragma unroll
    for (int i = 0; i < 9; i++)
        #pragma unroll
        for (int j = 0; j < 4; j++)
            acc[i][j] = 0.f;

    #pragma unroll
    for (int ks = 0; ks < 4; ks++) {
        uint32_t aF[4];
        ldmx4(aF, sQb + (wid * 16 + (lid & 15)) * AQ_B + ks * 32 + (lid >> 4) * 16);
        #pragma unroll
        for (int n2 = 0; n2 < 9; n2++) {
            uint32_t bF[2];
            const int n = n2 * 8 + (lid >> 2);
            bF[0] = sM[(ks * 8 + (lid & 3)) * SM_S + n];
            bF[1] = sM[(ks * 8 + 4 + (lid & 3)) * SM_S + n];
            mma16(acc[n2], aF, bF);
        }
    }

    const float den0 = __shfl_sync(0xffffffffu, acc[8][0], lid & ~3);
    const float den1 = __shfl_sync(0xffffffffu, acc[8][2], lid & ~3);
    const float z0 = 1.f / (den0 + EPS_F);
    const float z1 = 1.f / (den1 + EPS_F);

    const int arow = tile * 128 + wid * 16 + (lid >> 2);
    const size_t base = ((size_t)bs * ALEN + arow) * EMB + h * HDIM;
    #pragma unroll
    for (int n2 = 0; n2 < 8; n2++) {
        const int col = n2 * 8 + (lid & 3) * 2;
        *(uint32_t*)(AO + base + col) = packh2(z0 * acc[n2][0], z0 * acc[n2][1]);
        *(uint32_t*)(AO + base + (size_t)8 * EMB + col) =
            packh2(z1 * acc[n2][2], z1 * acc[n2][3]);
    }
}

// ---------------------------------------------------------------------------
extern "C" void kernel_launch(void* const* d_in, const int* in_sizes, int n_in,
                              void* d_out, int out_size)
{
    const float* input_q  = (const float*)d_in[0];
    const float* input_kv = (const float*)d_in[1];
    const float* Wq = (const float*)d_in[2];
    const float* bq = (const float*)d_in[3];
    const float* Wk = (const float*)d_in[4];
    const float* bk = (const float*)d_in[5];
    const float* Wv = (const float*)d_in[6];
    const float* bv = (const float*)d_in[7];
    const float* Wo = (const float*)d_in[8];
    const float* bo = (const float*)d_in[9];
    float* out = (float*)d_out;

    void *p0, *p1, *p2, *p3, *p4, *p5, *p8, *p9, *p10;
    cudaGetSymbolAddress(&p0,  g_iqh);
    cudaGetSymbolAddress(&p1,  g_ikh);
    cudaGetSymbolAddress(&p2,  g_Qh);
    cudaGetSymbolAddress(&p3,  g_Kh);
    cudaGetSymbolAddress(&p4,  g_Vh);
    cudaGetSymbolAddress(&p5,  g_AOh);
    cudaGetSymbolAddress(&p8,  g_KtV);
    cudaGetSymbolAddress(&p9,  g_ksum);
    cudaGetSymbolAddress(&p10, g_Wf);
    __half*   iqh  = (__half*)p0;
    __half*   ikh  = (__half*)p1;
    __half*   Qh   = (__half*)p2;
    __half*   Kh   = (__half*)p3;
    __half*   Vh   = (__half*)p4;
    __half*   AOh  = (__half*)p5;
    float*    KtV  = (float*)p8;
    float*    ks   = (float*)p9;
    uint32_t* Wf   = (uint32_t*)p10;

    cudaFuncSetAttribute((const void*)gemm_h_kernel<0, 0, 0>,
                         cudaFuncAttributeMaxDynamicSharedMemorySize, GEMM_SMEM);
    cudaFuncSetAttribute((const void*)gemm_h_kernel<1, 1, 0>,
                         cudaFuncAttributeMaxDynamicSharedMemorySize, GEMM_SMEM);
    cudaFuncSetAttribute((const void*)gemm_h_kernel<0, 1, 1>,
                         cudaFuncAttributeMaxDynamicSharedMemorySize, GEMM_SMEM);
    cudaFuncSetAttribute((const void*)ktv_mma_kernel,
                         cudaFuncAttributeMaxDynamicSharedMemorySize, KTV_SMEM);
    cudaFuncSetAttribute((const void*)apply_h_kernel,
                         cudaFuncAttributeMaxDynamicSharedMemorySize, APPLY_SMEM);

    const size_t WSZ = 131072;

    // prep: one weight-pack launch + one input-convert launch
    wprep4_kernel<<<2048, 256>>>(Wq, Wk, Wv, Wo, Wf);
    aprep2_kernel<<<2 * APREP_BLKS_PER, 256>>>(input_q, iqh, input_kv, ikh);

    // Q projection (elu+1)
    gemm_h_kernel<1, 1, 0><<<dim3(2, M_TOK / 128), 256, GEMM_SMEM>>>(
        iqh, Wf + 0 * WSZ, bq, nullptr, Qh, nullptr);

    // Fused K+V projection (grid.x = 4: bx<2 -> K elu+1, bx>=2 -> V identity)
    gemm_h_kernel<0, 1, 1><<<dim3(4, M_TOK / 128), 256, GEMM_SMEM>>>(
        ikh, Wf + 1 * WSZ, bk, bv, Kh, Vh);

    ktv_mma_kernel<<<NGROUP, 256, KTV_SMEM>>>(Kh, Vh, KtV, ks);
    apply_h_kernel<<<dim3(ALEN / 128, NGROUP), 256, APPLY_SMEM>>>(Qh, KtV, ks, AOh);

    // Output projection (fp32 out)
    gemm_h_kernel<0, 0, 0><<<dim3(2, M_TOK / 128), 256, GEMM_SMEM>>>(
        AOh, Wf + 3 * WSZ, bo, nullptr, out, nullptr);
}

// round 12
// speedup vs baseline: 1.1278x; 1.1278x over previous
#include <cuda_runtime.h>
#include <cuda_fp16.h>
#include <cstdint>

// Problem constants
#define M_TOK   131072      // b*s*a = 2*32*2048
#define EMB     512
#define NHEAD   8
#define HDIM    64
#define NGROUP  512         // b*s*h = 64*8
#define ALEN    2048
#define EPS_F   1e-6f

// Scratch (device globals: allocation-free per harness rules)
__device__ __half   g_iqh[(size_t)M_TOK * EMB];
__device__ __half   g_ikh[(size_t)M_TOK * EMB];
__device__ __half   g_Kh [(size_t)M_TOK * EMB];
__device__ __half   g_Vh [(size_t)M_TOK * EMB];
__device__ __half   g_AOh[(size_t)M_TOK * EMB];
__device__ uint32_t g_KtVh[(size_t)NGROUP * 2304];  // packed fp16 [g][d2(32)][e(72)]
__device__ uint32_t g_Wf [4 * (size_t)131072];      // fragment-packed fp16 weights

// ---------------------------------------------------------------------------
__device__ __forceinline__ void mma16(float* d, const uint32_t* a, const uint32_t* b) {
    asm volatile(
        "mma.sync.aligned.m16n8k16.row.col.f32.f16.f16.f32 "
        "{%0,%1,%2,%3},{%4,%5,%6,%7},{%8,%9},{%0,%1,%2,%3};"
        : "+f"(d[0]), "+f"(d[1]), "+f"(d[2]), "+f"(d[3])
        : "r"(a[0]), "r"(a[1]), "r"(a[2]), "r"(a[3]),
          "r"(b[0]), "r"(b[1]));
}

__device__ __forceinline__ void ldmx4(uint32_t* r, uint32_t addr) {
    asm volatile("ldmatrix.sync.aligned.m8n8.x4.shared.b16 {%0,%1,%2,%3}, [%4];"
                 : "=r"(r[0]), "=r"(r[1]), "=r"(r[2]), "=r"(r[3]) : "r"(addr));
}
__device__ __forceinline__ void ldmx4t(uint32_t* r, uint32_t addr) {
    asm volatile("ldmatrix.sync.aligned.m8n8.x4.trans.shared.b16 {%0,%1,%2,%3}, [%4];"
                 : "=r"(r[0]), "=r"(r[1]), "=r"(r[2]), "=r"(r[3]) : "r"(addr));
}
__device__ __forceinline__ void ldmx2t(uint32_t* r, uint32_t addr) {
    asm volatile("ldmatrix.sync.aligned.m8n8.x2.trans.shared.b16 {%0,%1}, [%2];"
                 : "=r"(r[0]), "=r"(r[1]) : "r"(addr));
}

__device__ __forceinline__ uint32_t smem_u32(const void* p) {
    uint32_t a;
    asm("{ .reg .u64 t; cvta.to.shared.u64 t, %1; cvt.u32.u64 %0, t; }"
        : "=r"(a) : "l"(p));
    return a;
}

__device__ __forceinline__ void cp16(uint32_t dst, const void* src) {
    asm volatile("cp.async.cg.shared.global [%0], [%1], 16;"
                 :: "r"(dst), "l"(src) : "memory");
}
#define CP_COMMIT() asm volatile("cp.async.commit_group;" ::: "memory")
#define CP_WAIT1()  asm volatile("cp.async.wait_group 1;" ::: "memory")
#define CP_WAIT0()  asm volatile("cp.async.wait_group 0;" ::: "memory")

__device__ __forceinline__ uint32_t packh2(float a, float b) {
    __half2 h = __floats2half2_rn(a, b);
    return *(uint32_t*)&h;
}
__device__ __forceinline__ float elu1(float v) {
    return v > 0.f ? v + 1.f : expf(v);
}

// Fragment mapping (m16n8k16, validated):
//   A: lane l, reg rg: pairs A[(l>>2)+8*(rg&1)][(l&3)*2 + 8*(rg>>1) + {0,1}]
//   B: lane l, reg rg: pairs B[k=(l&3)*2+8*rg+{0,1}][n=(l>>2)]
//   C: lane l, reg c:  row=(l>>2)+8*(c>>1), col=(l&3)*2+(c&1)
// KEY: C-fragment (row, col-pair) == A-fragment (row, k-pair) -> chained mma.

// ===========================================================================
// Prep: fp32 -> fp16 for both inputs in ONE launch
// ===========================================================================
#define APREP_BLKS_PER 32768
__global__ __launch_bounds__(256)
void aprep2_kernel(const float* __restrict__ s0, __half* __restrict__ d0,
                   const float* __restrict__ s1, __half* __restrict__ d1)
{
    const int b = blockIdx.x;
    const float* src = (b < APREP_BLKS_PER) ? s0 : s1;
    __half*      dst = (b < APREP_BLKS_PER) ? d0 : d1;
    const size_t i = ((size_t)(b & (APREP_BLKS_PER - 1)) * 256 + threadIdx.x) * 8;
    const float4 a = *(const float4*)(src + i);
    const float4 c = *(const float4*)(src + i + 4);
    __half2 h[4];
    h[0] = __floats2half2_rn(a.x, a.y);
    h[1] = __floats2half2_rn(a.z, a.w);
    h[2] = __floats2half2_rn(c.x, c.y);
    h[3] = __floats2half2_rn(c.z, c.w);
    *(uint4*)(dst + i) = *(uint4*)h;
}

// ===========================================================================
// Weight prep — all 4 weights in ONE launch
// ===========================================================================
__global__ __launch_bounds__(256)
void wprep4_kernel(const float* __restrict__ W0, const float* __restrict__ W1,
                   const float* __restrict__ W2, const float* __restrict__ W3,
                   uint32_t* __restrict__ Wf)
{
    const int w   = blockIdx.x >> 9;
    const float* W = (w == 0) ? W0 : (w == 1) ? W1 : (w == 2) ? W2 : W3;
    const int o   = (blockIdx.x & 511) * 256 + threadIdx.x;
    const int rg  = o & 1;
    const int l   = (o >> 1) & 31;
    const int ntg = (o >> 6) & 63;
    const int ks  = (o >> 12) & 3;
    const int c   = o >> 14;
    const int k0  = c * 64 + ks * 16 + (l & 3) * 2 + 8 * rg;
    const int n   = ntg * 8 + (l >> 2);
    Wf[(size_t)w * 131072 + o] =
        packh2(W[(size_t)k0 * EMB + n], W[(size_t)(k0 + 1) * EMB + n]);
}

// ===========================================================================
// Shared GEMM config (R10-validated: 3-stage, 32x64 warp tile, 2 CTAs/SM)
// ===========================================================================
#define AS_B    144
#define A_STG   (128 * 36)
#define B_STG   4096
#define STG_W   (A_STG + B_STG)
#define GEMM_SMEM (3 * STG_W * 4)     // 104448 B; 2 CTAs fit

// issue helper shared by both gemm kernels (as macro-like lambda pattern)

// ===========================================================================
// fp16 mma GEMM (KV fused / plain). Exactly R10's kernel.
// KV=0: grid.x=4, C = act(A @ Wf[bx]) + bias
// KV=1: grid.x=8 fused K/V: bx<4 -> K (elu+1, ->Cv0), bx>=4 -> V (->Cv1)
// ===========================================================================
template<int ACT, int OUTH, int KV>
__global__ __launch_bounds__(256, 2)
void gemm_h_kernel(const __half* __restrict__ Ah,
                   const uint32_t* __restrict__ WfBase,
                   const float* __restrict__ bias0,
                   const float* __restrict__ bias1,
                   void* __restrict__ Cv0,
                   void* __restrict__ Cv1)
{
    extern __shared__ uint32_t sm[];
    const uint32_t smb = smem_u32(sm);

    const int t   = threadIdx.x;
    const int lid = t & 31;
    const int wid = t >> 5;
    const int wr  = wid >> 1;
    const int wc  = wid & 1;
    const int bxr = blockIdx.x;
    const int isV = KV ? (bxr >= 4) : 0;
    const int bx  = KV ? (bxr & 3) : bxr;
    const int bm  = blockIdx.y * 128;

    const uint32_t* Wf = WfBase + (KV && isV ? (size_t)131072 : 0);
    const float* bias  = (KV && isV) ? bias1 : bias0;
    void* Cv           = (KV && isV) ? Cv1 : Cv0;
    const int act      = KV ? !isV : ACT;

    const uint4* W4 = (const uint4*)Wf;

    auto issue = [&](int c, int s) {
        const uint32_t st = smb + (uint32_t)s * (STG_W * 4);
        #pragma unroll
        for (int i = 0; i < 4; i++) {
            const int id  = t + i * 256;
            const int row = id >> 3;
            const int j   = id & 7;
            cp16(st + row * AS_B + j * 16,
                 Ah + (size_t)(bm + row) * EMB + c * 64 + j * 8);
        }
        #pragma unroll
        for (int i = 0; i < 4; i++) {
            const int id   = t + i * 256;
            const int ks   = id >> 8;
            const int rest = id & 255;
            cp16(st + (A_STG + ks * 1024) * 4 + rest * 16,
                 W4 + (size_t)((c * 4 + ks) * 64 + bx * 16) * 16 + rest);
        }
        CP_COMMIT();
    };

    float acc[2][8][4];
    #pragma unroll
    for (int i = 0; i < 2; i++)
        #pragma unroll
        for (int j = 0; j < 8; j++)
            #pragma unroll
            for (int k = 0; k < 4; k++)
                acc[i][j][k] = 0.f;

    issue(0, 0);
    issue(1, 1);

    for (int c = 0; c < 8; c++) {
        const int s = c % 3;
        if (c >= 6) { CP_WAIT0(); } else { CP_WAIT1(); }
        __syncthreads();
        if (c + 2 < 8) issue(c + 2, (c + 2) % 3);

        const uint32_t stA = smb + (uint32_t)s * (STG_W * 4);
        const uint32_t* Bb = sm + s * STG_W + A_STG;

        #pragma unroll
        for (int ks = 0; ks < 4; ks++) {
            uint32_t aF[2][4];
            #pragma unroll
            for (int m2 = 0; m2 < 2; m2++)
                ldmx4(aF[m2], stA + (wr * 32 + m2 * 16 + (lid & 15)) * AS_B
                               + ks * 32 + (lid >> 4) * 16);
            uint32_t bF[8][2];
            #pragma unroll
            for (int n2 = 0; n2 < 8; n2++) {
                const uint2 v = *(const uint2*)
                    &Bb[ks * 1024 + (wc * 8 + n2) * 64 + lid * 2];
                bF[n2][0] = v.x; bF[n2][1] = v.y;
            }
            #pragma unroll
            for (int m2 = 0; m2 < 2; m2++)
                #pragma unroll
                for (int n2 = 0; n2 < 8; n2++)
                    mma16(acc[m2][n2], aF[m2], bF[n2]);
        }
    }

    const int bn = bx * 128;
    const int r0 = bm + wr * 32 + (lid >> 2);
    #pragma unroll
    for (int m2 = 0; m2 < 2; m2++) {
        const int row = r0 + m2 * 16;
        #pragma unroll
        for (int n2 = 0; n2 < 8; n2++) {
            const int col = bn + wc * 64 + n2 * 8 + (lid & 3) * 2;
            const float b0 = __ldg(bias + col);
            const float b1 = __ldg(bias + col + 1);
            float v0 = acc[m2][n2][0] + b0;
            float v1 = acc[m2][n2][1] + b1;
            float v2 = acc[m2][n2][2] + b0;
            float v3 = acc[m2][n2][3] + b1;
            if (act) {
                v0 = elu1(v0); v1 = elu1(v1); v2 = elu1(v2); v3 = elu1(v3);
            }
            if (OUTH) {
                __half* Ch = (__half*)Cv;
                *(uint32_t*)(Ch + (size_t)row * EMB + col)       = packh2(v0, v1);
                *(uint32_t*)(Ch + (size_t)(row + 8) * EMB + col) = packh2(v2, v3);
            } else {
                float* Cf = (float*)Cv;
                float2 o0; o0.x = v0; o0.y = v1;
                float2 o1; o1.x = v2; o1.y = v3;
                *(float2*)(Cf + (size_t)row * EMB + col) = o0;
                *(float2*)(Cf + (size_t)(row + 8) * EMB + col) = o1;
            }
        }
    }
}

// ===========================================================================
// FUSED Q-projection + linear-attention apply.
// Mainloop identical to gemm_h (grid.x=4). Each warp's 32x64 C slab = one
// head's q for 32 tokens (head = bx*2 + wc). Epilogue: bias+elu, pack C
// fragments directly into A fragments, mma against packed [KtV|ksum] loaded
// from g_KtVh into dead stage-0 smem, z-normalize, write AOh fp16.
// ===========================================================================
__global__ __launch_bounds__(256, 2)
void gemm_q_apply_kernel(const __half* __restrict__ Ah,
                         const uint32_t* __restrict__ Wf,
                         const float* __restrict__ bias,
                         const uint32_t* __restrict__ KtVh,
                         __half* __restrict__ AO)
{
    extern __shared__ uint32_t sm[];
    const uint32_t smb = smem_u32(sm);

    const int t   = threadIdx.x;
    const int lid = t & 31;
    const int wid = t >> 5;
    const int wr  = wid >> 1;
    const int wc  = wid & 1;
    const int bx  = blockIdx.x;          // 0..3
    const int bm  = blockIdx.y * 128;

    const uint4* W4 = (const uint4*)Wf;

    auto issue = [&](int c, int s) {
        const uint32_t st = smb + (uint32_t)s * (STG_W * 4);
        #pragma unroll
        for (int i = 0; i < 4; i++) {
            const int id  = t + i * 256;
            const int row = id >> 3;
            const int j   = id & 7;
            cp16(st + row * AS_B + j * 16,
                 Ah + (size_t)(bm + row) * EMB + c * 64 + j * 8);
        }
        #pragma unroll
        for (int i = 0; i < 4; i++) {
            const int id   = t + i * 256;
            const int ks   = id >> 8;
            const int rest = id & 255;
            cp16(st + (A_STG + ks * 1024) * 4 + rest * 16,
                 W4 + (size_t)((c * 4 + ks) * 64 + bx * 16) * 16 + rest);
        }
        CP_COMMIT();
    };

    float acc[2][8][4];
    #pragma unroll
    for (int i = 0; i < 2; i++)
        #pragma unroll
        for (int j = 0; j < 8; j++)
            #pragma unroll
            for (int k = 0; k < 4; k++)
                acc[i][j][k] = 0.f;

    issue(0, 0);
    issue(1, 1);

    for (int c = 0; c < 8; c++) {
        const int s = c % 3;
        if (c >= 6) { CP_WAIT0(); } else { CP_WAIT1(); }
        __syncthreads();
        if (c + 2 < 8) issue(c + 2, (c + 2) % 3);

        const uint32_t stA = smb + (uint32_t)s * (STG_W * 4);
        const uint32_t* Bb = sm + s * STG_W + A_STG;

        #pragma unroll
        for (int ks = 0; ks < 4; ks++) {
            uint32_t aF[2][4];
            #pragma unroll
            for (int m2 = 0; m2 < 2; m2++)
                ldmx4(aF[m2], stA + (wr * 32 + m2 * 16 + (lid & 15)) * AS_B
                               + ks * 32 + (lid >> 4) * 16);
            uint32_t bF[8][2];
            #pragma unroll
            for (int n2 = 0; n2 < 8; n2++) {
                const uint2 v = *(const uint2*)
                    &Bb[ks * 1024 + (wc * 8 + n2) * 64 + lid * 2];
                bF[n2][0] = v.x; bF[n2][1] = v.y;
            }
            #pragma unroll
            for (int m2 = 0; m2 < 2; m2++)
                #pragma unroll
                for (int n2 = 0; n2 < 8; n2++)
                    mma16(acc[m2][n2], aF[m2], bF[n2]);
        }
    }

    // ---- fused apply epilogue ----
    __syncthreads();
    // load packed [KtV|ksum] for heads bx*2, bx*2+1 of this bs into stage 0
    {
        const int bs_ = bm >> 11;   // bm / 2048
        const uint32_t* src = KtVh + ((size_t)bs_ * NHEAD + bx * 2) * 2304;
        for (int i = t; i < 4608; i += 256) sm[i] = src[i];
    }
    __syncthreads();
    const uint32_t* sM = sm + wc * 2304;   // this warp's head
    const int head = bx * 2 + wc;
    const int bn = bx * 128;

    #pragma unroll
    for (int m2 = 0; m2 < 2; m2++) {
        // bias + elu+1 in place
        #pragma unroll
        for (int n2 = 0; n2 < 8; n2++) {
            const int col = bn + wc * 64 + n2 * 8 + (lid & 3) * 2;
            const float b0 = __ldg(bias + col);
            const float b1 = __ldg(bias + col + 1);
            acc[m2][n2][0] = elu1(acc[m2][n2][0] + b0);
            acc[m2][n2][1] = elu1(acc[m2][n2][1] + b1);
            acc[m2][n2][2] = elu1(acc[m2][n2][2] + b0);
            acc[m2][n2][3] = elu1(acc[m2][n2][3] + b1);
        }
        // pack C fragments -> A fragments (per ks: n-tiles 2ks, 2ks+1)
        uint32_t qf[4][4];
        #pragma unroll
        for (int ks = 0; ks < 4; ks++) {
            qf[ks][0] = packh2(acc[m2][2 * ks][0],     acc[m2][2 * ks][1]);
            qf[ks][1] = packh2(acc[m2][2 * ks][2],     acc[m2][2 * ks][3]);
            qf[ks][2] = packh2(acc[m2][2 * ks + 1][0], acc[m2][2 * ks + 1][1]);
            qf[ks][3] = packh2(acc[m2][2 * ks + 1][2], acc[m2][2 * ks + 1][3]);
        }
        // q @ [KtV | ksum]
        float a2[9][4];
        #pragma unroll
        for (int i = 0; i < 9; i++)
            #pragma unroll
            for (int j = 0; j < 4; j++)
                a2[i][j] = 0.f;
        #pragma unroll
        for (int ks = 0; ks < 4; ks++) {
            #pragma unroll
            for (int n2 = 0; n2 < 9; n2++) {
                uint32_t bF[2];
                const int n = n2 * 8 + (lid >> 2);
                bF[0] = sM[(ks * 8 + (lid & 3)) * 72 + n];
                bF[1] = sM[(ks * 8 + 4 + (lid & 3)) * 72 + n];
                mma16(a2[n2], qf[ks], bF);
            }
        }
        // z from col 64, scale, store
        const float den0 = __shfl_sync(0xffffffffu, a2[8][0], lid & ~3);
        const float den1 = __shfl_sync(0xffffffffu, a2[8][2], lid & ~3);
        const float z0 = 1.f / (den0 + EPS_F);
        const float z1 = 1.f / (den1 + EPS_F);

        const int row = bm + wr * 32 + m2 * 16 + (lid >> 2);
        const size_t base = (size_t)row * EMB + head * HDIM;
        #pragma unroll
        for (int n2 = 0; n2 < 8; n2++) {
            const int col = n2 * 8 + (lid & 3) * 2;
            *(uint32_t*)(AO + base + col) = packh2(z0 * a2[n2][0], z0 * a2[n2][1]);
            *(uint32_t*)(AO + base + (size_t)8 * EMB + col) =
                packh2(z1 * a2[n2][2], z1 * a2[n2][3]);
        }
    }
}

// ===========================================================================
// Tensorized KtV + ksum -> packed fp16 output g_KtVh[g][d2][e]
// (u32 at (d2,e) = pack(KtV[2*d2][e], KtV[2*d2+1][e]); col 64 = ksum; 65-71=0)
// ===========================================================================
#define KTV_KST   9216
#define KTV_VST   11264
#define KTV_STG   (KTV_KST + KTV_VST)
#define KTV_SMEM  (3 * KTV_STG)

__global__ __launch_bounds__(256)
void ktv_mma_kernel(const __half* __restrict__ Kp,
                    const __half* __restrict__ Vp,
                    uint32_t* __restrict__ KtVh)
{
    extern __shared__ uint32_t sm[];
    const uint32_t smb = smem_u32(sm);

    const int g  = blockIdx.x;
    const int bs = g >> 3;
    const int h  = g & 7;
    const size_t rowbase = (size_t)bs * ALEN;
    const int coff = h * HDIM;

    const int t   = threadIdx.x;
    const int lid = t & 31;
    const int wid = t >> 5;
    const int mt  = wid >> 1;
    const int nh  = wid & 1;
    const int ntc = 5 - nh;
    const int n0  = nh * 40;

    if (t < 64) {
        #pragma unroll
        for (int s = 0; s < 3; s++) {
            __half* vb = (__half*)((char*)sm + s * KTV_STG + KTV_KST);
            vb[t * 88 + 64] = __float2half(1.0f);
        }
    }

    auto issue = [&](int c, int s) {
        const uint32_t stK = smb + (uint32_t)s * KTV_STG;
        const uint32_t stV = stK + KTV_KST;
        const int a0 = c * 64;
        #pragma unroll
        for (int i = 0; i < 2; i++) {
            const int id  = t + i * 256;
            const int row = id >> 3;
            const int j   = id & 7;
            const size_t goff = (rowbase + a0 + row) * EMB + coff + j * 8;
            cp16(stK + row * 144 + j * 16, Kp + goff);
            cp16(stV + row * 176 + j * 16, Vp + goff);
        }
        CP_COMMIT();
    };

    float acc[5][4];
    #pragma unroll
    for (int i = 0; i < 5; i++)
        #pragma unroll
        for (int j = 0; j < 4; j++)
            acc[i][j] = 0.f;

    const int g2 = lid >> 3;
    const int l8 = lid & 7;
    const int a_rowA = (g2 >> 1) * 8 + l8;
    const int a_colA = mt * 16 + (g2 & 1) * 8;
    const int a_rowB = (g2 & 1) * 8 + l8;
    const int a_colB = (g2 >> 1) * 8;
    const int a_rowB2 = ((lid >> 3) & 1) * 8 + l8;

    issue(0, 0);
    issue(1, 1);

    for (int c = 0; c < 32; c++) {
        const int s = c % 3;
        if (c >= 30) { CP_WAIT0(); } else { CP_WAIT1(); }
        __syncthreads();
        if (c + 2 < 32) issue(c + 2, (c + 2) % 3);

        const uint32_t stK = smb + (uint32_t)s * KTV_STG;
        const uint32_t stV = stK + KTV_KST;

        #pragma unroll
        for (int ks = 0; ks < 4; ks++) {
            uint32_t aF[4];
            ldmx4t(aF, stK + (ks * 16 + a_rowA) * 144 + a_colA * 2);

            uint32_t bF[5][2];
            {
                uint32_t r4[4];
                ldmx4t(r4, stV + (ks * 16 + a_rowB) * 176 + (n0 + a_colB) * 2);
                bF[0][0] = r4[0]; bF[0][1] = r4[1];
                bF[1][0] = r4[2]; bF[1][1] = r4[3];
                ldmx4t(r4, stV + (ks * 16 + a_rowB) * 176 + (n0 + 16 + a_colB) * 2);
                bF[2][0] = r4[0]; bF[2][1] = r4[1];
                bF[3][0] = r4[2]; bF[3][1] = r4[3];
            }
            if (nh == 0) {
                uint32_t r2[2];
                ldmx2t(r2, stV + (ks * 16 + a_rowB2) * 176 + (n0 + 32) * 2);
                bF[4][0] = r2[0]; bF[4][1] = r2[1];
            }

            #pragma unroll
            for (int nt = 0; nt < 4; nt++)
                mma16(acc[nt], aF, bF[nt]);
            if (nh == 0)
                mma16(acc[4], aF, bF[4]);
        }
    }

    // epilogue: pack d-pairs via shfl-xor(4) and store packed fp16
    uint32_t* Kout = KtVh + (size_t)g * 2304;
    const int r2 = lid >> 2;
    #pragma unroll
    for (int nt = 0; nt < 5; nt++) {
        if (nt >= ntc) break;
        const int n = n0 + nt * 8;
        #pragma unroll
        for (int c = 0; c < 4; c++) {
            const float v  = acc[nt][c];
            const float vo = __shfl_xor_sync(0xffffffffu, v, 4);
            if ((r2 & 1) == 0) {
                const int d2 = mt * 8 + (r2 >> 1) + 4 * (c >> 1);
                const int e  = n + (lid & 3) * 2 + (c & 1);
                if (e <= 64) Kout[d2 * 72 + e] = packh2(v, vo);
            }
        }
    }
    // zero pad cols 65..71
    if (t < 224) Kout[(t / 7) * 72 + 65 + (t % 7)] = 0u;
}

// ---------------------------------------------------------------------------
extern "C" void kernel_launch(void* const* d_in, const int* in_sizes, int n_in,
                              void* d_out, int out_size)
{
    const float* input_q  = (const float*)d_in[0];
    const float* input_kv = (const float*)d_in[1];
    const float* Wq = (const float*)d_in[2];
    const float* bq = (const float*)d_in[3];
    const float* Wk = (const float*)d_in[4];
    const float* bk = (const float*)d_in[5];
    const float* Wv = (const float*)d_in[6];
    const float* bv = (const float*)d_in[7];
    const float* Wo = (const float*)d_in[8];
    const float* bo = (const float*)d_in[9];
    float* out = (float*)d_out;

    void *p0, *p1, *p3, *p4, *p5, *p8, *p10;
    cudaGetSymbolAddress(&p0,  g_iqh);
    cudaGetSymbolAddress(&p1,  g_ikh);
    cudaGetSymbolAddress(&p3,  g_Kh);
    cudaGetSymbolAddress(&p4,  g_Vh);
    cudaGetSymbolAddress(&p5,  g_AOh);
    cudaGetSymbolAddress(&p8,  g_KtVh);
    cudaGetSymbolAddress(&p10, g_Wf);
    __half*   iqh  = (__half*)p0;
    __half*   ikh  = (__half*)p1;
    __half*   Kh   = (__half*)p3;
    __half*   Vh   = (__half*)p4;
    __half*   AOh  = (__half*)p5;
    uint32_t* KtVh = (uint32_t*)p8;
    uint32_t* Wf   = (uint32_t*)p10;

    cudaFuncSetAttribute((const void*)gemm_h_kernel<0, 0, 0>,
                         cudaFuncAttributeMaxDynamicSharedMemorySize, GEMM_SMEM);
    cudaFuncSetAttribute((const void*)gemm_h_kernel<0, 1, 1>,
                         cudaFuncAttributeMaxDynamicSharedMemorySize, GEMM_SMEM);
    cudaFuncSetAttribute((const void*)gemm_q_apply_kernel,
                         cudaFuncAttributeMaxDynamicSharedMemorySize, GEMM_SMEM);
    cudaFuncSetAttribute((const void*)ktv_mma_kernel,
                         cudaFuncAttributeMaxDynamicSharedMemorySize, KTV_SMEM);

    const size_t WSZ = 131072;

    // prep
    wprep4_kernel<<<2048, 256>>>(Wq, Wk, Wv, Wo, Wf);
    aprep2_kernel<<<2 * APREP_BLKS_PER, 256>>>(input_q, iqh, input_kv, ikh);

    // Fused K+V projection
    gemm_h_kernel<0, 1, 1><<<dim3(8, M_TOK / 128), 256, GEMM_SMEM>>>(
        ikh, Wf + 1 * WSZ, bk, bv, Kh, Vh);

    // KtV + ksum (packed fp16 output)
    ktv_mma_kernel<<<NGROUP, 256, KTV_SMEM>>>(Kh, Vh, KtVh);

    // Fused Q projection + apply (writes AOh)
    gemm_q_apply_kernel<<<dim3(4, M_TOK / 128), 256, GEMM_SMEM>>>(
        iqh, Wf + 0 * WSZ, bq, KtVh, AOh);

    // Output projection (fp32 out)
    gemm_h_kernel<0, 0, 0><<<dim3(4, M_TOK / 128), 256, GEMM_SMEM>>>(
        AOh, Wf + 3 * WSZ, bo, nullptr, out, nullptr);
}

// round 13
// speedup vs baseline: 1.1293x; 1.0013x over previous
#include <cuda_runtime.h>
#include <cuda_fp16.h>
#include <cstdint>

// Problem constants
#define M_TOK   131072      // b*s*a = 2*32*2048
#define EMB     512
#define NHEAD   8
#define HDIM    64
#define NGROUP  512         // b*s*h = 64*8
#define ALEN    2048
#define EPS_F   1e-6f

// Scratch (device globals: allocation-free per harness rules)
__device__ __half   g_iqh[(size_t)M_TOK * EMB];
__device__ __half   g_ikh[(size_t)M_TOK * EMB];
__device__ __half   g_Kh [(size_t)M_TOK * EMB];
__device__ __half   g_Vh [(size_t)M_TOK * EMB];
__device__ __half   g_AOh[(size_t)M_TOK * EMB];
__device__ uint32_t g_KtVh[(size_t)NGROUP * 2304];  // packed fp16 [g][d2(32)][e(72)]
__device__ uint32_t g_Wf [4 * (size_t)131072];      // fragment-packed fp16 weights

// ---------------------------------------------------------------------------
__device__ __forceinline__ void mma16(float* d, const uint32_t* a, const uint32_t* b) {
    asm volatile(
        "mma.sync.aligned.m16n8k16.row.col.f32.f16.f16.f32 "
        "{%0,%1,%2,%3},{%4,%5,%6,%7},{%8,%9},{%0,%1,%2,%3};"
        : "+f"(d[0]), "+f"(d[1]), "+f"(d[2]), "+f"(d[3])
        : "r"(a[0]), "r"(a[1]), "r"(a[2]), "r"(a[3]),
          "r"(b[0]), "r"(b[1]));
}

__device__ __forceinline__ void ldmx4(uint32_t* r, uint32_t addr) {
    asm volatile("ldmatrix.sync.aligned.m8n8.x4.shared.b16 {%0,%1,%2,%3}, [%4];"
                 : "=r"(r[0]), "=r"(r[1]), "=r"(r[2]), "=r"(r[3]) : "r"(addr));
}
__device__ __forceinline__ void ldmx4t(uint32_t* r, uint32_t addr) {
    asm volatile("ldmatrix.sync.aligned.m8n8.x4.trans.shared.b16 {%0,%1,%2,%3}, [%4];"
                 : "=r"(r[0]), "=r"(r[1]), "=r"(r[2]), "=r"(r[3]) : "r"(addr));
}
__device__ __forceinline__ void ldmx2t(uint32_t* r, uint32_t addr) {
    asm volatile("ldmatrix.sync.aligned.m8n8.x2.trans.shared.b16 {%0,%1}, [%2];"
                 : "=r"(r[0]), "=r"(r[1]) : "r"(addr));
}

__device__ __forceinline__ uint32_t smem_u32(const void* p) {
    uint32_t a;
    asm("{ .reg .u64 t; cvta.to.shared.u64 t, %1; cvt.u32.u64 %0, t; }"
        : "=r"(a) : "l"(p));
    return a;
}

__device__ __forceinline__ void cp16(uint32_t dst, const void* src) {
    asm volatile("cp.async.cg.shared.global [%0], [%1], 16;"
                 :: "r"(dst), "l"(src) : "memory");
}
#define CP_COMMIT() asm volatile("cp.async.commit_group;" ::: "memory")
#define CP_WAIT1()  asm volatile("cp.async.wait_group 1;" ::: "memory")
#define CP_WAIT0()  asm volatile("cp.async.wait_group 0;" ::: "memory")

__device__ __forceinline__ uint32_t packh2(float a, float b) {
    __half2 h = __floats2half2_rn(a, b);
    return *(uint32_t*)&h;
}
__device__ __forceinline__ float elu1(float v) {
    return v > 0.f ? v + 1.f : expf(v);
}

// Fragment mapping (m16n8k16, validated):
//   A: lane l, reg rg: pairs A[(l>>2)+8*(rg&1)][(l&3)*2 + 8*(rg>>1) + {0,1}]
//   B: lane l, reg rg: pairs B[k=(l&3)*2+8*rg+{0,1}][n=(l>>2)]
//   C: lane l, reg c:  row=(l>>2)+8*(c>>1), col=(l&3)*2+(c&1)
// KEY: C-fragment (row, col-pair) == A-fragment (row, k-pair) -> chained mma.

// ===========================================================================
// Prep: fp32 -> fp16 for both inputs in ONE launch
// ===========================================================================
#define APREP_BLKS_PER 32768
__global__ __launch_bounds__(256)
void aprep2_kernel(const float* __restrict__ s0, __half* __restrict__ d0,
                   const float* __restrict__ s1, __half* __restrict__ d1)
{
    const int b = blockIdx.x;
    const float* src = (b < APREP_BLKS_PER) ? s0 : s1;
    __half*      dst = (b < APREP_BLKS_PER) ? d0 : d1;
    const size_t i = ((size_t)(b & (APREP_BLKS_PER - 1)) * 256 + threadIdx.x) * 8;
    const float4 a = *(const float4*)(src + i);
    const float4 c = *(const float4*)(src + i + 4);
    __half2 h[4];
    h[0] = __floats2half2_rn(a.x, a.y);
    h[1] = __floats2half2_rn(a.z, a.w);
    h[2] = __floats2half2_rn(c.x, c.y);
    h[3] = __floats2half2_rn(c.z, c.w);
    *(uint4*)(dst + i) = *(uint4*)h;
}

// ===========================================================================
// Weight prep — all 4 weights in ONE launch
// ===========================================================================
__global__ __launch_bounds__(256)
void wprep4_kernel(const float* __restrict__ W0, const float* __restrict__ W1,
                   const float* __restrict__ W2, const float* __restrict__ W3,
                   uint32_t* __restrict__ Wf)
{
    const int w   = blockIdx.x >> 9;
    const float* W = (w == 0) ? W0 : (w == 1) ? W1 : (w == 2) ? W2 : W3;
    const int o   = (blockIdx.x & 511) * 256 + threadIdx.x;
    const int rg  = o & 1;
    const int l   = (o >> 1) & 31;
    const int ntg = (o >> 6) & 63;
    const int ks  = (o >> 12) & 3;
    const int c   = o >> 14;
    const int k0  = c * 64 + ks * 16 + (l & 3) * 2 + 8 * rg;
    const int n   = ntg * 8 + (l >> 2);
    Wf[(size_t)w * 131072 + o] =
        packh2(W[(size_t)k0 * EMB + n], W[(size_t)(k0 + 1) * EMB + n]);
}

// ===========================================================================
// Shared GEMM config (R10-validated: 3-stage, 32x64 warp tile, 2 CTAs/SM)
// ===========================================================================
#define AS_B    144
#define A_STG   (128 * 36)
#define B_STG   4096
#define STG_W   (A_STG + B_STG)
#define GEMM_SMEM (3 * STG_W * 4)     // 104448 B; 2 CTAs fit

// ===========================================================================
// fp16 mma GEMM (KV fused / plain). R10's validated kernel.
// ===========================================================================
template<int ACT, int OUTH, int KV>
__global__ __launch_bounds__(256, 2)
void gemm_h_kernel(const __half* __restrict__ Ah,
                   const uint32_t* __restrict__ WfBase,
                   const float* __restrict__ bias0,
                   const float* __restrict__ bias1,
                   void* __restrict__ Cv0,
                   void* __restrict__ Cv1)
{
    extern __shared__ uint32_t sm[];
    const uint32_t smb = smem_u32(sm);

    const int t   = threadIdx.x;
    const int lid = t & 31;
    const int wid = t >> 5;
    const int wr  = wid >> 1;
    const int wc  = wid & 1;
    const int bxr = blockIdx.x;
    const int isV = KV ? (bxr >= 4) : 0;
    const int bx  = KV ? (bxr & 3) : bxr;
    const int bm  = blockIdx.y * 128;

    const uint32_t* Wf = WfBase + (KV && isV ? (size_t)131072 : 0);
    const float* bias  = (KV && isV) ? bias1 : bias0;
    void* Cv           = (KV && isV) ? Cv1 : Cv0;
    const int act      = KV ? !isV : ACT;

    const uint4* W4 = (const uint4*)Wf;

    auto issue = [&](int c, int s) {
        const uint32_t st = smb + (uint32_t)s * (STG_W * 4);
        #pragma unroll
        for (int i = 0; i < 4; i++) {
            const int id  = t + i * 256;
            const int row = id >> 3;
            const int j   = id & 7;
            cp16(st + row * AS_B + j * 16,
                 Ah + (size_t)(bm + row) * EMB + c * 64 + j * 8);
        }
        #pragma unroll
        for (int i = 0; i < 4; i++) {
            const int id   = t + i * 256;
            const int ks   = id >> 8;
            const int rest = id & 255;
            cp16(st + (A_STG + ks * 1024) * 4 + rest * 16,
                 W4 + (size_t)((c * 4 + ks) * 64 + bx * 16) * 16 + rest);
        }
        CP_COMMIT();
    };

    float acc[2][8][4];
    #pragma unroll
    for (int i = 0; i < 2; i++)
        #pragma unroll
        for (int j = 0; j < 8; j++)
            #pragma unroll
            for (int k = 0; k < 4; k++)
                acc[i][j][k] = 0.f;

    issue(0, 0);
    issue(1, 1);

    for (int c = 0; c < 8; c++) {
        const int s = c % 3;
        if (c >= 6) { CP_WAIT0(); } else { CP_WAIT1(); }
        __syncthreads();
        if (c + 2 < 8) issue(c + 2, (c + 2) % 3);

        const uint32_t stA = smb + (uint32_t)s * (STG_W * 4);
        const uint32_t* Bb = sm + s * STG_W + A_STG;

        #pragma unroll
        for (int ks = 0; ks < 4; ks++) {
            uint32_t aF[2][4];
            #pragma unroll
            for (int m2 = 0; m2 < 2; m2++)
                ldmx4(aF[m2], stA + (wr * 32 + m2 * 16 + (lid & 15)) * AS_B
                               + ks * 32 + (lid >> 4) * 16);
            uint32_t bF[8][2];
            #pragma unroll
            for (int n2 = 0; n2 < 8; n2++) {
                const uint2 v = *(const uint2*)
                    &Bb[ks * 1024 + (wc * 8 + n2) * 64 + lid * 2];
                bF[n2][0] = v.x; bF[n2][1] = v.y;
            }
            #pragma unroll
            for (int m2 = 0; m2 < 2; m2++)
                #pragma unroll
                for (int n2 = 0; n2 < 8; n2++)
                    mma16(acc[m2][n2], aF[m2], bF[n2]);
        }
    }

    const int bn = bx * 128;
    const int r0 = bm + wr * 32 + (lid >> 2);
    #pragma unroll
    for (int m2 = 0; m2 < 2; m2++) {
        const int row = r0 + m2 * 16;
        #pragma unroll
        for (int n2 = 0; n2 < 8; n2++) {
            const int col = bn + wc * 64 + n2 * 8 + (lid & 3) * 2;
            const float b0 = __ldg(bias + col);
            const float b1 = __ldg(bias + col + 1);
            float v0 = acc[m2][n2][0] + b0;
            float v1 = acc[m2][n2][1] + b1;
            float v2 = acc[m2][n2][2] + b0;
            float v3 = acc[m2][n2][3] + b1;
            if (act) {
                v0 = elu1(v0); v1 = elu1(v1); v2 = elu1(v2); v3 = elu1(v3);
            }
            if (OUTH) {
                __half* Ch = (__half*)Cv;
                *(uint32_t*)(Ch + (size_t)row * EMB + col)       = packh2(v0, v1);
                *(uint32_t*)(Ch + (size_t)(row + 8) * EMB + col) = packh2(v2, v3);
            } else {
                float* Cf = (float*)Cv;
                float2 o0; o0.x = v0; o0.y = v1;
                float2 o1; o1.x = v2; o1.y = v3;
                *(float2*)(Cf + (size_t)row * EMB + col) = o0;
                *(float2*)(Cf + (size_t)(row + 8) * EMB + col) = o1;
            }
        }
    }
}

// ===========================================================================
// FUSED Q-projection + linear-attention apply (register-lean epilogue).
// Per m2: bias+elu in place; pack qf; compute DENOMINATOR tile first -> z;
// then stream n-tiles 0..7: 4 mma -> scale -> store -> retire. Max live set:
// acc(64) fading + qf(16) + one a2 tile(4) + z(2): no spills at 128-reg cap.
// ===========================================================================
__global__ __launch_bounds__(256, 2)
void gemm_q_apply_kernel(const __half* __restrict__ Ah,
                         const uint32_t* __restrict__ Wf,
                         const float* __restrict__ bias,
                         const uint32_t* __restrict__ KtVh,
                         __half* __restrict__ AO)
{
    extern __shared__ uint32_t sm[];
    const uint32_t smb = smem_u32(sm);

    const int t   = threadIdx.x;
    const int lid = t & 31;
    const int wid = t >> 5;
    const int wr  = wid >> 1;
    const int wc  = wid & 1;
    const int bx  = blockIdx.x;          // 0..3
    const int bm  = blockIdx.y * 128;

    const uint4* W4 = (const uint4*)Wf;

    auto issue = [&](int c, int s) {
        const uint32_t st = smb + (uint32_t)s * (STG_W * 4);
        #pragma unroll
        for (int i = 0; i < 4; i++) {
            const int id  = t + i * 256;
            const int row = id >> 3;
            const int j   = id & 7;
            cp16(st + row * AS_B + j * 16,
                 Ah + (size_t)(bm + row) * EMB + c * 64 + j * 8);
        }
        #pragma unroll
        for (int i = 0; i < 4; i++) {
            const int id   = t + i * 256;
            const int ks   = id >> 8;
            const int rest = id & 255;
            cp16(st + (A_STG + ks * 1024) * 4 + rest * 16,
                 W4 + (size_t)((c * 4 + ks) * 64 + bx * 16) * 16 + rest);
        }
        CP_COMMIT();
    };

    float acc[2][8][4];
    #pragma unroll
    for (int i = 0; i < 2; i++)
        #pragma unroll
        for (int j = 0; j < 8; j++)
            #pragma unroll
            for (int k = 0; k < 4; k++)
                acc[i][j][k] = 0.f;

    issue(0, 0);
    issue(1, 1);

    for (int c = 0; c < 8; c++) {
        const int s = c % 3;
        if (c >= 6) { CP_WAIT0(); } else { CP_WAIT1(); }
        __syncthreads();
        if (c + 2 < 8) issue(c + 2, (c + 2) % 3);

        const uint32_t stA = smb + (uint32_t)s * (STG_W * 4);
        const uint32_t* Bb = sm + s * STG_W + A_STG;

        #pragma unroll
        for (int ks = 0; ks < 4; ks++) {
            uint32_t aF[2][4];
            #pragma unroll
            for (int m2 = 0; m2 < 2; m2++)
                ldmx4(aF[m2], stA + (wr * 32 + m2 * 16 + (lid & 15)) * AS_B
                               + ks * 32 + (lid >> 4) * 16);
            uint32_t bF[8][2];
            #pragma unroll
            for (int n2 = 0; n2 < 8; n2++) {
                const uint2 v = *(const uint2*)
                    &Bb[ks * 1024 + (wc * 8 + n2) * 64 + lid * 2];
                bF[n2][0] = v.x; bF[n2][1] = v.y;
            }
            #pragma unroll
            for (int m2 = 0; m2 < 2; m2++)
                #pragma unroll
                for (int n2 = 0; n2 < 8; n2++)
                    mma16(acc[m2][n2], aF[m2], bF[n2]);
        }
    }

    // ---- fused apply epilogue (register-lean) ----
    __syncthreads();
    {
        const int bs_ = bm >> 11;
        const uint32_t* src = KtVh + ((size_t)bs_ * NHEAD + bx * 2) * 2304;
        for (int i = t; i < 4608; i += 256) sm[i] = src[i];
    }
    __syncthreads();
    const uint32_t* sM = sm + wc * 2304;   // this warp's head
    const int head = bx * 2 + wc;
    const int bn = bx * 128;

    #pragma unroll
    for (int m2 = 0; m2 < 2; m2++) {
        // bias + elu+1 in place
        #pragma unroll
        for (int n2 = 0; n2 < 8; n2++) {
            const int col = bn + wc * 64 + n2 * 8 + (lid & 3) * 2;
            const float b0 = __ldg(bias + col);
            const float b1 = __ldg(bias + col + 1);
            acc[m2][n2][0] = elu1(acc[m2][n2][0] + b0);
            acc[m2][n2][1] = elu1(acc[m2][n2][1] + b1);
            acc[m2][n2][2] = elu1(acc[m2][n2][2] + b0);
            acc[m2][n2][3] = elu1(acc[m2][n2][3] + b1);
        }
        // pack C fragments -> A fragments
        uint32_t qf[4][4];
        #pragma unroll
        for (int ks = 0; ks < 4; ks++) {
            qf[ks][0] = packh2(acc[m2][2 * ks][0],     acc[m2][2 * ks][1]);
            qf[ks][1] = packh2(acc[m2][2 * ks][2],     acc[m2][2 * ks][3]);
            qf[ks][2] = packh2(acc[m2][2 * ks + 1][0], acc[m2][2 * ks + 1][1]);
            qf[ks][3] = packh2(acc[m2][2 * ks + 1][2], acc[m2][2 * ks + 1][3]);
        }
        // denominator tile first (n2 = 8) -> z
        float z0, z1;
        {
            float dden[4] = {0.f, 0.f, 0.f, 0.f};
            #pragma unroll
            for (int ks = 0; ks < 4; ks++) {
                uint32_t bF[2];
                const int n = 64 + (lid >> 2);
                bF[0] = sM[(ks * 8 + (lid & 3)) * 72 + n];
                bF[1] = sM[(ks * 8 + 4 + (lid & 3)) * 72 + n];
                mma16(dden, qf[ks], bF);
            }
            const float den0 = __shfl_sync(0xffffffffu, dden[0], lid & ~3);
            const float den1 = __shfl_sync(0xffffffffu, dden[2], lid & ~3);
            z0 = 1.f / (den0 + EPS_F);
            z1 = 1.f / (den1 + EPS_F);
        }
        // stream n-tiles 0..7: compute, scale, store, retire
        const int row = bm + wr * 32 + m2 * 16 + (lid >> 2);
        const size_t base = (size_t)row * EMB + head * HDIM;
        #pragma unroll
        for (int n2 = 0; n2 < 8; n2++) {
            float a2[4] = {0.f, 0.f, 0.f, 0.f};
            const int n = n2 * 8 + (lid >> 2);
            #pragma unroll
            for (int ks = 0; ks < 4; ks++) {
                uint32_t bF[2];
                bF[0] = sM[(ks * 8 + (lid & 3)) * 72 + n];
                bF[1] = sM[(ks * 8 + 4 + (lid & 3)) * 72 + n];
                mma16(a2, qf[ks], bF);
            }
            const int col = n2 * 8 + (lid & 3) * 2;
            *(uint32_t*)(AO + base + col) = packh2(z0 * a2[0], z0 * a2[1]);
            *(uint32_t*)(AO + base + (size_t)8 * EMB + col) =
                packh2(z1 * a2[2], z1 * a2[3]);
        }
    }
}

// ===========================================================================
// Tensorized KtV + ksum -> packed fp16 output g_KtVh[g][d2][e]  (validated)
// ===========================================================================
#define KTV_KST   9216
#define KTV_VST   11264
#define KTV_STG   (KTV_KST + KTV_VST)
#define KTV_SMEM  (3 * KTV_STG)

__global__ __launch_bounds__(256)
void ktv_mma_kernel(const __half* __restrict__ Kp,
                    const __half* __restrict__ Vp,
                    uint32_t* __restrict__ KtVh)
{
    extern __shared__ uint32_t sm[];
    const uint32_t smb = smem_u32(sm);

    const int g  = blockIdx.x;
    const int bs = g >> 3;
    const int h  = g & 7;
    const size_t rowbase = (size_t)bs * ALEN;
    const int coff = h * HDIM;

    const int t   = threadIdx.x;
    const int lid = t & 31;
    const int wid = t >> 5;
    const int mt  = wid >> 1;
    const int nh  = wid & 1;
    const int ntc = 5 - nh;
    const int n0  = nh * 40;

    if (t < 64) {
        #pragma unroll
        for (int s = 0; s < 3; s++) {
            __half* vb = (__half*)((char*)sm + s * KTV_STG + KTV_KST);
            vb[t * 88 + 64] = __float2half(1.0f);
        }
    }

    auto issue = [&](int c, int s) {
        const uint32_t stK = smb + (uint32_t)s * KTV_STG;
        const uint32_t stV = stK + KTV_KST;
        const int a0 = c * 64;
        #pragma unroll
        for (int i = 0; i < 2; i++) {
            const int id  = t + i * 256;
            const int row = id >> 3;
            const int j   = id & 7;
            const size_t goff = (rowbase + a0 + row) * EMB + coff + j * 8;
            cp16(stK + row * 144 + j * 16, Kp + goff);
            cp16(stV + row * 176 + j * 16, Vp + goff);
        }
        CP_COMMIT();
    };

    float acc[5][4];
    #pragma unroll
    for (int i = 0; i < 5; i++)
        #pragma unroll
        for (int j = 0; j < 4; j++)
            acc[i][j] = 0.f;

    const int g2 = lid >> 3;
    const int l8 = lid & 7;
    const int a_rowA = (g2 >> 1) * 8 + l8;
    const int a_colA = mt * 16 + (g2 & 1) * 8;
    const int a_rowB = (g2 & 1) * 8 + l8;
    const int a_colB = (g2 >> 1) * 8;
    const int a_rowB2 = ((lid >> 3) & 1) * 8 + l8;

    issue(0, 0);
    issue(1, 1);

    for (int c = 0; c < 32; c++) {
        const int s = c % 3;
        if (c >= 30) { CP_WAIT0(); } else { CP_WAIT1(); }
        __syncthreads();
        if (c + 2 < 32) issue(c + 2, (c + 2) % 3);

        const uint32_t stK = smb + (uint32_t)s * KTV_STG;
        const uint32_t stV = stK + KTV_KST;

        #pragma unroll
        for (int ks = 0; ks < 4; ks++) {
            uint32_t aF[4];
            ldmx4t(aF, stK + (ks * 16 + a_rowA) * 144 + a_colA * 2);

            uint32_t bF[5][2];
            {
                uint32_t r4[4];
                ldmx4t(r4, stV + (ks * 16 + a_rowB) * 176 + (n0 + a_colB) * 2);
                bF[0][0] = r4[0]; bF[0][1] = r4[1];
                bF[1][0] = r4[2]; bF[1][1] = r4[3];
                ldmx4t(r4, stV + (ks * 16 + a_rowB) * 176 + (n0 + 16 + a_colB) * 2);
                bF[2][0] = r4[0]; bF[2][1] = r4[1];
                bF[3][0] = r4[2]; bF[3][1] = r4[3];
            }
            if (nh == 0) {
                uint32_t r2[2];
                ldmx2t(r2, stV + (ks * 16 + a_rowB2) * 176 + (n0 + 32) * 2);
                bF[4][0] = r2[0]; bF[4][1] = r2[1];
            }

            #pragma unroll
            for (int nt = 0; nt < 4; nt++)
                mma16(acc[nt], aF, bF[nt]);
            if (nh == 0)
                mma16(acc[4], aF, bF[4]);
        }
    }

    // epilogue: pack d-pairs via shfl-xor(4) and store packed fp16
    uint32_t* Kout = KtVh + (size_t)g * 2304;
    const int r2 = lid >> 2;
    #pragma unroll
    for (int nt = 0; nt < 5; nt++) {
        if (nt >= ntc) break;
        const int n = n0 + nt * 8;
        #pragma unroll
        for (int c = 0; c < 4; c++) {
            const float v  = acc[nt][c];
            const float vo = __shfl_xor_sync(0xffffffffu, v, 4);
            if ((r2 & 1) == 0) {
                const int d2 = mt * 8 + (r2 >> 1) + 4 * (c >> 1);
                const int e  = n + (lid & 3) * 2 + (c & 1);
                if (e <= 64) Kout[d2 * 72 + e] = packh2(v, vo);
            }
        }
    }
    // zero pad cols 65..71
    if (t < 224) Kout[(t / 7) * 72 + 65 + (t % 7)] = 0u;
}

// ---------------------------------------------------------------------------
extern "C" void kernel_launch(void* const* d_in, const int* in_sizes, int n_in,
                              void* d_out, int out_size)
{
    const float* input_q  = (const float*)d_in[0];
    const float* input_kv = (const float*)d_in[1];
    const float* Wq = (const float*)d_in[2];
    const float* bq = (const float*)d_in[3];
    const float* Wk = (const float*)d_in[4];
    const float* bk = (const float*)d_in[5];
    const float* Wv = (const float*)d_in[6];
    const float* bv = (const float*)d_in[7];
    const float* Wo = (const float*)d_in[8];
    const float* bo = (const float*)d_in[9];
    float* out = (float*)d_out;

    void *p0, *p1, *p3, *p4, *p5, *p8, *p10;
    cudaGetSymbolAddress(&p0,  g_iqh);
    cudaGetSymbolAddress(&p1,  g_ikh);
    cudaGetSymbolAddress(&p3,  g_Kh);
    cudaGetSymbolAddress(&p4,  g_Vh);
    cudaGetSymbolAddress(&p5,  g_AOh);
    cudaGetSymbolAddress(&p8,  g_KtVh);
    cudaGetSymbolAddress(&p10, g_Wf);
    __half*   iqh  = (__half*)p0;
    __half*   ikh  = (__half*)p1;
    __half*   Kh   = (__half*)p3;
    __half*   Vh   = (__half*)p4;
    __half*   AOh  = (__half*)p5;
    uint32_t* KtVh = (uint32_t*)p8;
    uint32_t* Wf   = (uint32_t*)p10;

    cudaFuncSetAttribute((const void*)gemm_h_kernel<0, 0, 0>,
                         cudaFuncAttributeMaxDynamicSharedMemorySize, GEMM_SMEM);
    cudaFuncSetAttribute((const void*)gemm_h_kernel<0, 1, 1>,
                         cudaFuncAttributeMaxDynamicSharedMemorySize, GEMM_SMEM);
    cudaFuncSetAttribute((const void*)gemm_q_apply_kernel,
                         cudaFuncAttributeMaxDynamicSharedMemorySize, GEMM_SMEM);
    cudaFuncSetAttribute((const void*)ktv_mma_kernel,
                         cudaFuncAttributeMaxDynamicSharedMemorySize, KTV_SMEM);

    const size_t WSZ = 131072;

    // prep
    wprep4_kernel<<<2048, 256>>>(Wq, Wk, Wv, Wo, Wf);
    aprep2_kernel<<<2 * APREP_BLKS_PER, 256>>>(input_q, iqh, input_kv, ikh);

    // Fused K+V projection
    gemm_h_kernel<0, 1, 1><<<dim3(8, M_TOK / 128), 256, GEMM_SMEM>>>(
        ikh, Wf + 1 * WSZ, bk, bv, Kh, Vh);

    // KtV + ksum (packed fp16 output)
    ktv_mma_kernel<<<NGROUP, 256, KTV_SMEM>>>(Kh, Vh, KtVh);

    // Fused Q projection + apply (writes AOh)
    gemm_q_apply_kernel<<<dim3(4, M_TOK / 128), 256, GEMM_SMEM>>>(
        iqh, Wf + 0 * WSZ, bq, KtVh, AOh);

    // Output projection (fp32 out)
    gemm_h_kernel<0, 0, 0><<<dim3(4, M_TOK / 128), 256, GEMM_SMEM>>>(
        AOh, Wf + 3 * WSZ, bo, nullptr, out, nullptr);
}

// round 14
// speedup vs baseline: 1.1631x; 1.0300x over previous
#include <cuda_runtime.h>
#include <cuda_fp16.h>
#include <cstdint>

// Problem constants
#define M_TOK   131072      // b*s*a = 2*32*2048
#define EMB     512
#define NHEAD   8
#define HDIM    64
#define NGROUP  512         // b*s*h = 64*8
#define ALEN    2048
#define EPS_F   1e-6f

// Scratch (device globals: allocation-free per harness rules)
__device__ __half   g_iqh[(size_t)M_TOK * EMB];
__device__ __half   g_ikh[(size_t)M_TOK * EMB];
__device__ __half   g_Qh [(size_t)M_TOK * EMB];
__device__ __half   g_Kh [(size_t)M_TOK * EMB];
__device__ __half   g_Vh [(size_t)M_TOK * EMB];
__device__ __half   g_AOh[(size_t)M_TOK * EMB];
__device__ uint32_t g_KtVh[(size_t)NGROUP * 2304];  // packed fp16 [g][d2(32)][e(72)]
__device__ uint32_t g_Wf [4 * (size_t)131072];      // fragment-packed fp16 weights

// ---------------------------------------------------------------------------
__device__ __forceinline__ void mma16(float* d, const uint32_t* a, const uint32_t* b) {
    asm volatile(
        "mma.sync.aligned.m16n8k16.row.col.f32.f16.f16.f32 "
        "{%0,%1,%2,%3},{%4,%5,%6,%7},{%8,%9},{%0,%1,%2,%3};"
        : "+f"(d[0]), "+f"(d[1]), "+f"(d[2]), "+f"(d[3])
        : "r"(a[0]), "r"(a[1]), "r"(a[2]), "r"(a[3]),
          "r"(b[0]), "r"(b[1]));
}

__device__ __forceinline__ void ldmx4(uint32_t* r, uint32_t addr) {
    asm volatile("ldmatrix.sync.aligned.m8n8.x4.shared.b16 {%0,%1,%2,%3}, [%4];"
                 : "=r"(r[0]), "=r"(r[1]), "=r"(r[2]), "=r"(r[3]) : "r"(addr));
}
__device__ __forceinline__ void ldmx4t(uint32_t* r, uint32_t addr) {
    asm volatile("ldmatrix.sync.aligned.m8n8.x4.trans.shared.b16 {%0,%1,%2,%3}, [%4];"
                 : "=r"(r[0]), "=r"(r[1]), "=r"(r[2]), "=r"(r[3]) : "r"(addr));
}
__device__ __forceinline__ void ldmx2t(uint32_t* r, uint32_t addr) {
    asm volatile("ldmatrix.sync.aligned.m8n8.x2.trans.shared.b16 {%0,%1}, [%2];"
                 : "=r"(r[0]), "=r"(r[1]) : "r"(addr));
}

__device__ __forceinline__ uint32_t smem_u32(const void* p) {
    uint32_t a;
    asm("{ .reg .u64 t; cvta.to.shared.u64 t, %1; cvt.u32.u64 %0, t; }"
        : "=r"(a) : "l"(p));
    return a;
}

__device__ __forceinline__ void cp16(uint32_t dst, const void* src) {
    asm volatile("cp.async.cg.shared.global [%0], [%1], 16;"
                 :: "r"(dst), "l"(src) : "memory");
}
#define CP_COMMIT() asm volatile("cp.async.commit_group;" ::: "memory")
#define CP_WAIT1()  asm volatile("cp.async.wait_group 1;" ::: "memory")
#define CP_WAIT0()  asm volatile("cp.async.wait_group 0;" ::: "memory")

__device__ __forceinline__ uint32_t packh2(float a, float b) {
    __half2 h = __floats2half2_rn(a, b);
    return *(uint32_t*)&h;
}
__device__ __forceinline__ float elu1(float v) {
    return v > 0.f ? v + 1.f : expf(v);
}

// Fragment mapping (m16n8k16, validated):
//   A: lane l, reg rg: pairs A[(l>>2)+8*(rg&1)][(l&3)*2 + 8*(rg>>1) + {0,1}]
//   B: lane l, reg rg: pairs B[k=(l&3)*2+8*rg+{0,1}][n=(l>>2)]
//   C: lane l, reg c:  row=(l>>2)+8*(c>>1), col=(l&3)*2+(c&1)

// ===========================================================================
// Prep: fp32 -> fp16 for both inputs in ONE launch
// ===========================================================================
#define APREP_BLKS_PER 32768
__global__ __launch_bounds__(256)
void aprep2_kernel(const float* __restrict__ s0, __half* __restrict__ d0,
                   const float* __restrict__ s1, __half* __restrict__ d1)
{
    const int b = blockIdx.x;
    const float* src = (b < APREP_BLKS_PER) ? s0 : s1;
    __half*      dst = (b < APREP_BLKS_PER) ? d0 : d1;
    const size_t i = ((size_t)(b & (APREP_BLKS_PER - 1)) * 256 + threadIdx.x) * 8;
    const float4 a = *(const float4*)(src + i);
    const float4 c = *(const float4*)(src + i + 4);
    __half2 h[4];
    h[0] = __floats2half2_rn(a.x, a.y);
    h[1] = __floats2half2_rn(a.z, a.w);
    h[2] = __floats2half2_rn(c.x, c.y);
    h[3] = __floats2half2_rn(c.z, c.w);
    *(uint4*)(dst + i) = *(uint4*)h;
}

// ===========================================================================
// Weight prep — all 4 weights in ONE launch
// ===========================================================================
__global__ __launch_bounds__(256)
void wprep4_kernel(const float* __restrict__ W0, const float* __restrict__ W1,
                   const float* __restrict__ W2, const float* __restrict__ W3,
                   uint32_t* __restrict__ Wf)
{
    const int w   = blockIdx.x >> 9;
    const float* W = (w == 0) ? W0 : (w == 1) ? W1 : (w == 2) ? W2 : W3;
    const int o   = (blockIdx.x & 511) * 256 + threadIdx.x;
    const int rg  = o & 1;
    const int l   = (o >> 1) & 31;
    const int ntg = (o >> 6) & 63;
    const int ks  = (o >> 12) & 3;
    const int c   = o >> 14;
    const int k0  = c * 64 + ks * 16 + (l & 3) * 2 + 8 * rg;
    const int n   = ntg * 8 + (l >> 2);
    Wf[(size_t)w * 131072 + o] =
        packh2(W[(size_t)k0 * EMB + n], W[(size_t)(k0 + 1) * EMB + n]);
}

// ===========================================================================
// Shared GEMM config (R10-validated: 3-stage, 32x64 warp tile)
// ===========================================================================
#define AS_B    144
#define A_STG   (128 * 36)
#define B_STG   4096
#define STG_W   (A_STG + B_STG)
#define GEMM_SMEM (3 * STG_W * 4)     // 104448 B; 2 CTAs fit

// ===========================================================================
// MERGED Q/K/V projection GEMM — one launch, grid.x = 12.
//   w = bx>>2 : 0 -> Q (A=iqh, Wq, bq, out Qh, elu+1)
//               1 -> K (A=ikh, Wk, bk, out Kh, elu+1)
//               2 -> V (A=ikh, Wv, bv, out Vh, identity)
//   bxn = bx&3 selects the 128-col N slice.
// Mainloop identical to the validated R10 kernel.
// ===========================================================================
__global__ __launch_bounds__(256, 2)
void gemm_qkv_kernel(const __half* __restrict__ iq,
                     const __half* __restrict__ ik,
                     const uint32_t* __restrict__ WfBase,
                     const float* __restrict__ bq,
                     const float* __restrict__ bk,
                     const float* __restrict__ bv,
                     __half* __restrict__ Qo,
                     __half* __restrict__ Ko,
                     __half* __restrict__ Vo)
{
    extern __shared__ uint32_t sm[];
    const uint32_t smb = smem_u32(sm);

    const int t   = threadIdx.x;
    const int lid = t & 31;
    const int wid = t >> 5;
    const int wr  = wid >> 1;
    const int wc  = wid & 1;
    const int bxr = blockIdx.x;          // 0..11
    const int w   = bxr >> 2;            // 0..2
    const int bx  = bxr & 3;
    const int bm  = blockIdx.y * 128;

    const __half* Ah   = (w == 0) ? iq : ik;
    const uint32_t* Wf = WfBase + (size_t)w * 131072;
    const float* bias  = (w == 0) ? bq : (w == 1) ? bk : bv;
    __half* Cv         = (w == 0) ? Qo : (w == 1) ? Ko : Vo;
    const int act      = (w < 2);

    const uint4* W4 = (const uint4*)Wf;

    auto issue = [&](int c, int s) {
        const uint32_t st = smb + (uint32_t)s * (STG_W * 4);
        #pragma unroll
        for (int i = 0; i < 4; i++) {
            const int id  = t + i * 256;
            const int row = id >> 3;
            const int j   = id & 7;
            cp16(st + row * AS_B + j * 16,
                 Ah + (size_t)(bm + row) * EMB + c * 64 + j * 8);
        }
        #pragma unroll
        for (int i = 0; i < 4; i++) {
            const int id   = t + i * 256;
            const int ks   = id >> 8;
            const int rest = id & 255;
            cp16(st + (A_STG + ks * 1024) * 4 + rest * 16,
                 W4 + (size_t)((c * 4 + ks) * 64 + bx * 16) * 16 + rest);
        }
        CP_COMMIT();
    };

    float acc[2][8][4];
    #pragma unroll
    for (int i = 0; i < 2; i++)
        #pragma unroll
        for (int j = 0; j < 8; j++)
            #pragma unroll
            for (int k = 0; k < 4; k++)
                acc[i][j][k] = 0.f;

    issue(0, 0);
    issue(1, 1);

    for (int c = 0; c < 8; c++) {
        const int s = c % 3;
        if (c >= 6) { CP_WAIT0(); } else { CP_WAIT1(); }
        __syncthreads();
        if (c + 2 < 8) issue(c + 2, (c + 2) % 3);

        const uint32_t stA = smb + (uint32_t)s * (STG_W * 4);
        const uint32_t* Bb = sm + s * STG_W + A_STG;

        #pragma unroll
        for (int ks = 0; ks < 4; ks++) {
            uint32_t aF[2][4];
            #pragma unroll
            for (int m2 = 0; m2 < 2; m2++)
                ldmx4(aF[m2], stA + (wr * 32 + m2 * 16 + (lid & 15)) * AS_B
                               + ks * 32 + (lid >> 4) * 16);
            uint32_t bF[8][2];
            #pragma unroll
            for (int n2 = 0; n2 < 8; n2++) {
                const uint2 v = *(const uint2*)
                    &Bb[ks * 1024 + (wc * 8 + n2) * 64 + lid * 2];
                bF[n2][0] = v.x; bF[n2][1] = v.y;
            }
            #pragma unroll
            for (int m2 = 0; m2 < 2; m2++)
                #pragma unroll
                for (int n2 = 0; n2 < 8; n2++)
                    mma16(acc[m2][n2], aF[m2], bF[n2]);
        }
    }

    const int bn = bx * 128;
    const int r0 = bm + wr * 32 + (lid >> 2);
    #pragma unroll
    for (int m2 = 0; m2 < 2; m2++) {
        const int row = r0 + m2 * 16;
        #pragma unroll
        for (int n2 = 0; n2 < 8; n2++) {
            const int col = bn + wc * 64 + n2 * 8 + (lid & 3) * 2;
            const float b0 = __ldg(bias + col);
            const float b1 = __ldg(bias + col + 1);
            float v0 = acc[m2][n2][0] + b0;
            float v1 = acc[m2][n2][1] + b1;
            float v2 = acc[m2][n2][2] + b0;
            float v3 = acc[m2][n2][3] + b1;
            if (act) {
                v0 = elu1(v0); v1 = elu1(v1); v2 = elu1(v2); v3 = elu1(v3);
            }
            *(uint32_t*)(Cv + (size_t)row * EMB + col)       = packh2(v0, v1);
            *(uint32_t*)(Cv + (size_t)(row + 8) * EMB + col) = packh2(v2, v3);
        }
    }
}

// ===========================================================================
// Output-projection GEMM (fp16 in, fp32 out) — R10 validated kernel.
// ===========================================================================
__global__ __launch_bounds__(256, 2)
void gemm_out_kernel(const __half* __restrict__ Ah,
                     const uint32_t* __restrict__ Wf,
                     const float* __restrict__ bias,
                     float* __restrict__ Cf)
{
    extern __shared__ uint32_t sm[];
    const uint32_t smb = smem_u32(sm);

    const int t   = threadIdx.x;
    const int lid = t & 31;
    const int wid = t >> 5;
    const int wr  = wid >> 1;
    const int wc  = wid & 1;
    const int bx  = blockIdx.x;
    const int bm  = blockIdx.y * 128;

    const uint4* W4 = (const uint4*)Wf;

    auto issue = [&](int c, int s) {
        const uint32_t st = smb + (uint32_t)s * (STG_W * 4);
        #pragma unroll
        for (int i = 0; i < 4; i++) {
            const int id  = t + i * 256;
            const int row = id >> 3;
            const int j   = id & 7;
            cp16(st + row * AS_B + j * 16,
                 Ah + (size_t)(bm + row) * EMB + c * 64 + j * 8);
        }
        #pragma unroll
        for (int i = 0; i < 4; i++) {
            const int id   = t + i * 256;
            const int ks   = id >> 8;
            const int rest = id & 255;
            cp16(st + (A_STG + ks * 1024) * 4 + rest * 16,
                 W4 + (size_t)((c * 4 + ks) * 64 + bx * 16) * 16 + rest);
        }
        CP_COMMIT();
    };

    float acc[2][8][4];
    #pragma unroll
    for (int i = 0; i < 2; i++)
        #pragma unroll
        for (int j = 0; j < 8; j++)
            #pragma unroll
            for (int k = 0; k < 4; k++)
                acc[i][j][k] = 0.f;

    issue(0, 0);
    issue(1, 1);

    for (int c = 0; c < 8; c++) {
        const int s = c % 3;
        if (c >= 6) { CP_WAIT0(); } else { CP_WAIT1(); }
        __syncthreads();
        if (c + 2 < 8) issue(c + 2, (c + 2) % 3);

        const uint32_t stA = smb + (uint32_t)s * (STG_W * 4);
        const uint32_t* Bb = sm + s * STG_W + A_STG;

        #pragma unroll
        for (int ks = 0; ks < 4; ks++) {
            uint32_t aF[2][4];
            #pragma unroll
            for (int m2 = 0; m2 < 2; m2++)
                ldmx4(aF[m2], stA + (wr * 32 + m2 * 16 + (lid & 15)) * AS_B
                               + ks * 32 + (lid >> 4) * 16);
            uint32_t bF[8][2];
            #pragma unroll
            for (int n2 = 0; n2 < 8; n2++) {
                const uint2 v = *(const uint2*)
                    &Bb[ks * 1024 + (wc * 8 + n2) * 64 + lid * 2];
                bF[n2][0] = v.x; bF[n2][1] = v.y;
            }
            #pragma unroll
            for (int m2 = 0; m2 < 2; m2++)
                #pragma unroll
                for (int n2 = 0; n2 < 8; n2++)
                    mma16(acc[m2][n2], aF[m2], bF[n2]);
        }
    }

    const int bn = bx * 128;
    const int r0 = bm + wr * 32 + (lid >> 2);
    #pragma unroll
    for (int m2 = 0; m2 < 2; m2++) {
        const int row = r0 + m2 * 16;
        #pragma unroll
        for (int n2 = 0; n2 < 8; n2++) {
            const int col = bn + wc * 64 + n2 * 8 + (lid & 3) * 2;
            const float b0 = __ldg(bias + col);
            const float b1 = __ldg(bias + col + 1);
            float2 o0; o0.x = acc[m2][n2][0] + b0; o0.y = acc[m2][n2][1] + b1;
            float2 o1; o1.x = acc[m2][n2][2] + b0; o1.y = acc[m2][n2][3] + b1;
            *(float2*)(Cf + (size_t)row * EMB + col) = o0;
            *(float2*)(Cf + (size_t)(row + 8) * EMB + col) = o1;
        }
    }
}

// ===========================================================================
// Tensorized KtV + ksum -> packed fp16 output g_KtVh[g][d2][e]  (validated)
// ===========================================================================
#define KTV_KST   9216
#define KTV_VST   11264
#define KTV_STG   (KTV_KST + KTV_VST)
#define KTV_SMEM  (3 * KTV_STG)

__global__ __launch_bounds__(256)
void ktv_mma_kernel(const __half* __restrict__ Kp,
                    const __half* __restrict__ Vp,
                    uint32_t* __restrict__ KtVh)
{
    extern __shared__ uint32_t sm[];
    const uint32_t smb = smem_u32(sm);

    const int g  = blockIdx.x;
    const int bs = g >> 3;
    const int h  = g & 7;
    const size_t rowbase = (size_t)bs * ALEN;
    const int coff = h * HDIM;

    const int t   = threadIdx.x;
    const int lid = t & 31;
    const int wid = t >> 5;
    const int mt  = wid >> 1;
    const int nh  = wid & 1;
    const int ntc = 5 - nh;
    const int n0  = nh * 40;

    if (t < 64) {
        #pragma unroll
        for (int s = 0; s < 3; s++) {
            __half* vb = (__half*)((char*)sm + s * KTV_STG + KTV_KST);
            vb[t * 88 + 64] = __float2half(1.0f);
        }
    }

    auto issue = [&](int c, int s) {
        const uint32_t stK = smb + (uint32_t)s * KTV_STG;
        const uint32_t stV = stK + KTV_KST;
        const int a0 = c * 64;
        #pragma unroll
        for (int i = 0; i < 2; i++) {
            const int id  = t + i * 256;
            const int row = id >> 3;
            const int j   = id & 7;
            const size_t goff = (rowbase + a0 + row) * EMB + coff + j * 8;
            cp16(stK + row * 144 + j * 16, Kp + goff);
            cp16(stV + row * 176 + j * 16, Vp + goff);
        }
        CP_COMMIT();
    };

    float acc[5][4];
    #pragma unroll
    for (int i = 0; i < 5; i++)
        #pragma unroll
        for (int j = 0; j < 4; j++)
            acc[i][j] = 0.f;

    const int g2 = lid >> 3;
    const int l8 = lid & 7;
    const int a_rowA = (g2 >> 1) * 8 + l8;
    const int a_colA = mt * 16 + (g2 & 1) * 8;
    const int a_rowB = (g2 & 1) * 8 + l8;
    const int a_colB = (g2 >> 1) * 8;
    const int a_rowB2 = ((lid >> 3) & 1) * 8 + l8;

    issue(0, 0);
    issue(1, 1);

    for (int c = 0; c < 32; c++) {
        const int s = c % 3;
        if (c >= 30) { CP_WAIT0(); } else { CP_WAIT1(); }
        __syncthreads();
        if (c + 2 < 32) issue(c + 2, (c + 2) % 3);

        const uint32_t stK = smb + (uint32_t)s * KTV_STG;
        const uint32_t stV = stK + KTV_KST;

        #pragma unroll
        for (int ks = 0; ks < 4; ks++) {
            uint32_t aF[4];
            ldmx4t(aF, stK + (ks * 16 + a_rowA) * 144 + a_colA * 2);

            uint32_t bF[5][2];
            {
                uint32_t r4[4];
                ldmx4t(r4, stV + (ks * 16 + a_rowB) * 176 + (n0 + a_colB) * 2);
                bF[0][0] = r4[0]; bF[0][1] = r4[1];
                bF[1][0] = r4[2]; bF[1][1] = r4[3];
                ldmx4t(r4, stV + (ks * 16 + a_rowB) * 176 + (n0 + 16 + a_colB) * 2);
                bF[2][0] = r4[0]; bF[2][1] = r4[1];
                bF[3][0] = r4[2]; bF[3][1] = r4[3];
            }
            if (nh == 0) {
                uint32_t r2[2];
                ldmx2t(r2, stV + (ks * 16 + a_rowB2) * 176 + (n0 + 32) * 2);
                bF[4][0] = r2[0]; bF[4][1] = r2[1];
            }

            #pragma unroll
            for (int nt = 0; nt < 4; nt++)
                mma16(acc[nt], aF, bF[nt]);
            if (nh == 0)
                mma16(acc[4], aF, bF[4]);
        }
    }

    // epilogue: pack d-pairs via shfl-xor(4) and store packed fp16
    uint32_t* Kout = KtVh + (size_t)g * 2304;
    const int r2 = lid >> 2;
    #pragma unroll
    for (int nt = 0; nt < 5; nt++) {
        if (nt >= ntc) break;
        const int n = n0 + nt * 8;
        #pragma unroll
        for (int c = 0; c < 4; c++) {
            const float v  = acc[nt][c];
            const float vo = __shfl_xor_sync(0xffffffffu, v, 4);
            if ((r2 & 1) == 0) {
                const int d2 = mt * 8 + (r2 >> 1) + 4 * (c >> 1);
                const int e  = n + (lid & 3) * 2 + (c & 1);
                if (e <= 64) Kout[d2 * 72 + e] = packh2(v, vo);
            }
        }
    }
    if (t < 224) Kout[(t / 7) * 72 + 65 + (t % 7)] = 0u;
}

// ===========================================================================
// fp16 tensorized apply — reads PACKED KtVh (plain copy into smem).
// ===========================================================================
#define AQ_B  144
#define SM_S  72
#define APPLY_SMEM ((128 * 36 + 32 * SM_S) * 4)   // 27648 B

__global__ __launch_bounds__(256, 4)
void apply_h_kernel(const __half* __restrict__ Qp,
                    const uint32_t* __restrict__ KtVh,
                    __half* __restrict__ AO)
{
    extern __shared__ uint32_t sm[];
    const uint32_t sQb = smem_u32(sm);
    uint32_t* sM = sm + 128 * 36;

    const int g    = blockIdx.y;
    const int tile = blockIdx.x;
    const int bs   = g >> 3;
    const int h    = g & 7;
    const int t    = threadIdx.x;
    const int lid  = t & 31;
    const int wid  = t >> 5;

    // packed [KtV|ksum|pad] copy (2304 u32 = 9 KB)
    {
        const uint32_t* src = KtVh + (size_t)g * 2304;
        #pragma unroll
        for (int i = t; i < 2304; i += 256) sM[i] = src[i];
    }
    // Q tile (rows of 64 fp16, stride 144 B)
    {
        #pragma unroll
        for (int i = 0; i < 4; i++) {
            const int id  = t + i * 256;
            const int row = id >> 3;
            const int j   = id & 7;
            const uint4 v = *(const uint4*)
                (Qp + ((size_t)bs * ALEN + tile * 128 + row) * EMB + h * HDIM + j * 8);
            *(uint4*)((char*)sm + row * AQ_B + j * 16) = v;
        }
    }
    __syncthreads();

    float acc[9][4];
    #pragma unroll
    for (int i = 0; i < 9; i++)
        #pragma unroll
        for (int j = 0; j < 4; j++)
            acc[i][j] = 0.f;

    #pragma unroll
    for (int ks = 0; ks < 4; ks++) {
        uint32_t aF[4];
        ldmx4(aF, sQb + (wid * 16 + (lid & 15)) * AQ_B + ks * 32 + (lid >> 4) * 16);
        #pragma unroll
        for (int n2 = 0; n2 < 9; n2++) {
            uint32_t bF[2];
            const int n = n2 * 8 + (lid >> 2);
            bF[0] = sM[(ks * 8 + (lid & 3)) * SM_S + n];
            bF[1] = sM[(ks * 8 + 4 + (lid & 3)) * SM_S + n];
            mma16(acc[n2], aF, bF);
        }
    }

    const float den0 = __shfl_sync(0xffffffffu, acc[8][0], lid & ~3);
    const float den1 = __shfl_sync(0xffffffffu, acc[8][2], lid & ~3);
    const float z0 = 1.f / (den0 + EPS_F);
    const float z1 = 1.f / (den1 + EPS_F);

    const int arow = tile * 128 + wid * 16 + (lid >> 2);
    const size_t base = ((size_t)bs * ALEN + arow) * EMB + h * HDIM;
    #pragma unroll
    for (int n2 = 0; n2 < 8; n2++) {
        const int col = n2 * 8 + (lid & 3) * 2;
        *(uint32_t*)(AO + base + col) = packh2(z0 * acc[n2][0], z0 * acc[n2][1]);
        *(uint32_t*)(AO + base + (size_t)8 * EMB + col) =
            packh2(z1 * acc[n2][2], z1 * acc[n2][3]);
    }
}

// ---------------------------------------------------------------------------
extern "C" void kernel_launch(void* const* d_in, const int* in_sizes, int n_in,
                              void* d_out, int out_size)
{
    const float* input_q  = (const float*)d_in[0];
    const float* input_kv = (const float*)d_in[1];
    const float* Wq = (const float*)d_in[2];
    const float* bq = (const float*)d_in[3];
    const float* Wk = (const float*)d_in[4];
    const float* bk = (const float*)d_in[5];
    const float* Wv = (const float*)d_in[6];
    const float* bv = (const float*)d_in[7];
    const float* Wo = (const float*)d_in[8];
    const float* bo = (const float*)d_in[9];
    float* out = (float*)d_out;

    void *p0, *p1, *p2, *p3, *p4, *p5, *p8, *p10;
    cudaGetSymbolAddress(&p0,  g_iqh);
    cudaGetSymbolAddress(&p1,  g_ikh);
    cudaGetSymbolAddress(&p2,  g_Qh);
    cudaGetSymbolAddress(&p3,  g_Kh);
    cudaGetSymbolAddress(&p4,  g_Vh);
    cudaGetSymbolAddress(&p5,  g_AOh);
    cudaGetSymbolAddress(&p8,  g_KtVh);
    cudaGetSymbolAddress(&p10, g_Wf);
    __half*   iqh  = (__half*)p0;
    __half*   ikh  = (__half*)p1;
    __half*   Qh   = (__half*)p2;
    __half*   Kh   = (__half*)p3;
    __half*   Vh   = (__half*)p4;
    __half*   AOh  = (__half*)p5;
    uint32_t* KtVh = (uint32_t*)p8;
    uint32_t* Wf   = (uint32_t*)p10;

    cudaFuncSetAttribute((const void*)gemm_qkv_kernel,
                         cudaFuncAttributeMaxDynamicSharedMemorySize, GEMM_SMEM);
    cudaFuncSetAttribute((const void*)gemm_out_kernel,
                         cudaFuncAttributeMaxDynamicSharedMemorySize, GEMM_SMEM);
    cudaFuncSetAttribute((const void*)ktv_mma_kernel,
                         cudaFuncAttributeMaxDynamicSharedMemorySize, KTV_SMEM);
    cudaFuncSetAttribute((const void*)apply_h_kernel,
                         cudaFuncAttributeMaxDynamicSharedMemorySize, APPLY_SMEM);

    const size_t WSZ = 131072;

    // prep: one weight-pack launch + one input-convert launch
    wprep4_kernel<<<2048, 256>>>(Wq, Wk, Wv, Wo, Wf);
    aprep2_kernel<<<2 * APREP_BLKS_PER, 256>>>(input_q, iqh, input_kv, ikh);

    // Merged Q+K+V projection (grid.x = 12)
    gemm_qkv_kernel<<<dim3(12, M_TOK / 128), 256, GEMM_SMEM>>>(
        iqh, ikh, Wf, bq, bk, bv, Qh, Kh, Vh);

    // KtV + ksum (packed fp16 output)
    ktv_mma_kernel<<<NGROUP, 256, KTV_SMEM>>>(Kh, Vh, KtVh);

    // apply (reads packed KtVh)
    apply_h_kernel<<<dim3(ALEN / 128, NGROUP), 256, APPLY_SMEM>>>(Qh, KtVh, AOh);

    // Output projection (fp32 out)
    gemm_out_kernel<<<dim3(4, M_TOK / 128), 256, GEMM_SMEM>>>(
        AOh, Wf + 3 * WSZ, bo, out);
}